// round 2
// baseline (speedup 1.0000x reference)
#include <cuda_runtime.h>
#include <math.h>
#include <float.h>

// Problem constants (fixed by the dataset):
//  B=1, N=8192 vertices, M=32*32*32=32768 grid points, Cin=32, Cout=64,
//  K=16 neighbors, edge_in=35 (32 feat + 3 rel_pos), Cprov=96 grid channels.
#define KNN_K   16
#define EDGE_IN 35
#define CIN     32
#define COUT    64
#define CPROV   96
#define MAXM    32768
#define SCALE   32.0f   // RES / (aabb_max - aabb_min), uniform

__device__ int g_knn[MAXM * KNN_K];

// ---------------------------------------------------------------------------
// Kernel 1: brute-force exact KNN. One thread per grid point, vertex tiles
// staged in shared (float4: x,y,z,|r|^2 in scaled coords). All lanes of a warp
// walk the same candidate index -> LDS broadcast.
// ---------------------------------------------------------------------------
#define KTILE 2048
__global__ __launch_bounds__(256) void knn_kernel(
    const float* __restrict__ verts, const float* __restrict__ gverts,
    int M, int N)
{
    __shared__ float4 sv[KTILE];
    int m = blockIdx.x * blockDim.x + threadIdx.x;
    float qx = 0.f, qy = 0.f, qz = 0.f;
    if (m < M) {
        qx = gverts[3*m+0] * SCALE;
        qy = gverts[3*m+1] * SCALE;
        qz = gverts[3*m+2] * SCALE;
    }
    float qq  = qx*qx + qy*qy + qz*qz;
    float m2x = -2.f*qx, m2y = -2.f*qy, m2z = -2.f*qz;

    float bv[KNN_K]; int bi[KNN_K];
#pragma unroll
    for (int j = 0; j < KNN_K; j++) { bv[j] = FLT_MAX; bi[j] = 0; }
    float wv = FLT_MAX; int ws = 0;

    for (int base = 0; base < N; base += KTILE) {
        int tl = min(KTILE, N - base);
        for (int t = threadIdx.x; t < tl; t += blockDim.x) {
            int n = base + t;
            float x = verts[3*n+0] * SCALE;
            float y = verts[3*n+1] * SCALE;
            float z = verts[3*n+2] * SCALE;
            sv[t] = make_float4(x, y, z, x*x + y*y + z*z);
        }
        __syncthreads();
        if (m < M) {
#pragma unroll 4
            for (int t = 0; t < tl; t++) {
                float4 v = sv[t];
                float d2 = fmaf(m2x, v.x, fmaf(m2y, v.y, fmaf(m2z, v.z, qq + v.w)));
                if (d2 < wv) {                 // strict < : earliest index wins ties
                    int n = base + t;
#pragma unroll
                    for (int j = 0; j < KNN_K; j++)
                        if (j == ws) { bv[j] = d2; bi[j] = n; }
                    wv = -FLT_MAX;
#pragma unroll
                    for (int j = 0; j < KNN_K; j++)
                        if (bv[j] > wv) { wv = bv[j]; ws = j; }
                }
            }
        }
        __syncthreads();
    }
    if (m < M) {
#pragma unroll
        for (int j = 0; j < KNN_K; j++) g_knn[m*KNN_K + j] = bi[j];
    }
}

// ---------------------------------------------------------------------------
// Kernel 2: gather + edge MLP + mean + out MLP. One warp per grid point;
// lane handles output channels j0=2*lane, j1=2*lane+1 (float2 weight loads).
// Edge layer-2 is hoisted past the mean over K (linear op commutes with mean):
// agg = mean_k(gelu(LN(e_k@ew1+eb1))) @ ew2 + eb2.
// Layer-1 weights are register-blocked over all 16 neighbors.
// ---------------------------------------------------------------------------
__device__ __forceinline__ float gelu_tanh(float x) {
    float x3 = x * x * x;
    return 0.5f * x * (1.0f + tanhf(0.7978845608028654f * fmaf(0.044715f, x3, x)));
}

#define WPB 8
__global__ __launch_bounds__(WPB*32) void mlp_kernel(
    const float* __restrict__ verts, const float* __restrict__ feats,
    const float* __restrict__ gverts, const float* __restrict__ gfeat,
    const float* __restrict__ ew1,  const float* __restrict__ eb1,
    const float* __restrict__ eg1,  const float* __restrict__ ebt1,
    const float* __restrict__ ew2,  const float* __restrict__ eb2,
    const float* __restrict__ ow1,  const float* __restrict__ ob1,
    const float* __restrict__ og1,  const float* __restrict__ obt1,
    const float* __restrict__ ow2,  const float* __restrict__ ob2,
    float* __restrict__ out, int M)
{
    __shared__ float sh_e[WPB][KNN_K][EDGE_IN + 1];  // neighbor edge features
    __shared__ float sh_s[WPB][COUT];                // staging vector (reused)
    __shared__ float sh_g[WPB][CPROV];               // grid (sinusoidal) features

    int w = threadIdx.x >> 5, lane = threadIdx.x & 31;
    int m = blockIdx.x * WPB + w;
    if (m >= M) return;   // uniform per warp

    float gx = gverts[3*m+0], gy = gverts[3*m+1], gz = gverts[3*m+2];

    int myn = 0;
    if (lane < KNN_K) myn = g_knn[m*KNN_K + lane];

    for (int i = lane; i < CPROV; i += 32) sh_g[w][i] = gfeat[m*CPROV + i];

    // stage e_k = [feat(32), rel_pos(3)] for all 16 neighbors
    for (int k = 0; k < KNN_K; k++) {
        int n = __shfl_sync(0xffffffffu, myn, k);
        sh_e[w][k][lane] = feats[n*CIN + lane];
        if (lane < 3) {
            float gc = (lane == 0) ? gx : ((lane == 1) ? gy : gz);
            sh_e[w][k][CIN + lane] = verts[n*3 + lane] - gc;
        }
    }
    __syncwarp();

    // ---- edge layer 1: 35 -> 64, register-blocked over K=16 neighbors ----
    float acc0[KNN_K], acc1[KNN_K];
#pragma unroll
    for (int k = 0; k < KNN_K; k++) { acc0[k] = 0.f; acc1[k] = 0.f; }
    const float2* w1 = (const float2*)ew1;
#pragma unroll 5
    for (int i = 0; i < EDGE_IN; i++) {
        float2 wv = w1[i*32 + lane];
#pragma unroll
        for (int k = 0; k < KNN_K; k++) {
            float ev = sh_e[w][k][i];
            acc0[k] = fmaf(ev, wv.x, acc0[k]);
            acc1[k] = fmaf(ev, wv.y, acc1[k]);
        }
    }

    float2 be1 = ((const float2*)eb1)[lane];
    float2 ge1 = ((const float2*)eg1)[lane];
    float2 bt1 = ((const float2*)ebt1)[lane];
    float gm0 = 0.f, gm1 = 0.f;
#pragma unroll
    for (int k = 0; k < KNN_K; k++) {
        float a0 = acc0[k] + be1.x, a1 = acc1[k] + be1.y;
        float s = a0 + a1, s2 = a0*a0 + a1*a1;
#pragma unroll
        for (int o = 16; o; o >>= 1) {
            s  += __shfl_xor_sync(0xffffffffu, s,  o);
            s2 += __shfl_xor_sync(0xffffffffu, s2, o);
        }
        float mean = s * (1.f/COUT);
        float inv  = rsqrtf(s2 * (1.f/COUT) - mean*mean + 1e-5f);
        a0 = (a0 - mean) * inv * ge1.x + bt1.x;
        a1 = (a1 - mean) * inv * ge1.y + bt1.y;
        gm0 += gelu_tanh(a0);
        gm1 += gelu_tanh(a1);
    }
    gm0 *= (1.f/KNN_K); gm1 *= (1.f/KNN_K);

    *(float2*)&sh_s[w][2*lane] = make_float2(gm0, gm1);
    __syncwarp();

    // ---- edge layer 2 (hoisted past mean): 64 -> 64 ----
    float2 be2 = ((const float2*)eb2)[lane];
    float agg0 = be2.x, agg1 = be2.y;
    const float2* w2 = (const float2*)ew2;
#pragma unroll 8
    for (int i = 0; i < COUT; i++) {
        float hv = sh_s[w][i];
        float2 wv = w2[i*32 + lane];
        agg0 = fmaf(hv, wv.x, agg0);
        agg1 = fmaf(hv, wv.y, agg1);
    }
    __syncwarp();
    *(float2*)&sh_s[w][2*lane] = make_float2(agg0, agg1);
    __syncwarp();

    // ---- out layer 1: [agg(64) | grid_feat(96)] -> 64 ----
    float2 bo1 = ((const float2*)ob1)[lane];
    float c0 = bo1.x, c1 = bo1.y;
    const float2* wo1 = (const float2*)ow1;
#pragma unroll 8
    for (int i = 0; i < COUT; i++) {
        float v = sh_s[w][i];
        float2 wv = wo1[i*32 + lane];
        c0 = fmaf(v, wv.x, c0);
        c1 = fmaf(v, wv.y, c1);
    }
#pragma unroll 8
    for (int i = 0; i < CPROV; i++) {
        float v = sh_g[w][i];
        float2 wv = wo1[(COUT + i)*32 + lane];
        c0 = fmaf(v, wv.x, c0);
        c1 = fmaf(v, wv.y, c1);
    }
    {
        float s = c0 + c1, s2 = c0*c0 + c1*c1;
#pragma unroll
        for (int o = 16; o; o >>= 1) {
            s  += __shfl_xor_sync(0xffffffffu, s,  o);
            s2 += __shfl_xor_sync(0xffffffffu, s2, o);
        }
        float mean = s * (1.f/COUT);
        float inv  = rsqrtf(s2 * (1.f/COUT) - mean*mean + 1e-5f);
        float2 go = ((const float2*)og1)[lane];
        float2 bo = ((const float2*)obt1)[lane];
        c0 = gelu_tanh((c0 - mean) * inv * go.x + bo.x);
        c1 = gelu_tanh((c1 - mean) * inv * go.y + bo.y);
    }
    __syncwarp();
    *(float2*)&sh_s[w][2*lane] = make_float2(c0, c1);
    __syncwarp();

    // ---- out layer 2: 64 -> 64 ----
    float2 bo2 = ((const float2*)ob2)[lane];
    float o0 = bo2.x, o1 = bo2.y;
    const float2* wo2 = (const float2*)ow2;
#pragma unroll 8
    for (int i = 0; i < COUT; i++) {
        float v = sh_s[w][i];
        float2 wv = wo2[i*32 + lane];
        o0 = fmaf(v, wv.x, o0);
        o1 = fmaf(v, wv.y, o1);
    }
    ((float2*)out)[m*32 + lane] = make_float2(o0, o1);
}

// ---------------------------------------------------------------------------
// Launch. Input order (metadata.txt / setup_inputs dict order):
//  0 vertices (1,N,3)  1 features (1,N,32)  2 grid_verts (M,3)  3 grid_feat (M,96)
//  4 ew1 (35,64) 5 eb1 6 eg1 7 ebt1 8 ew2 (64,64) 9 eb2
//  10 ow1 (160,64) 11 ob1 12 og1 13 obt1 14 ow2 (64,64) 15 ob2
// Output: (1,32,32,32,64) float32.
// ---------------------------------------------------------------------------
extern "C" void kernel_launch(void* const* d_in, const int* in_sizes, int n_in,
                              void* d_out, int out_size)
{
    const float* verts  = (const float*)d_in[0];
    const float* feats  = (const float*)d_in[1];
    const float* gverts = (const float*)d_in[2];
    const float* gfeat  = (const float*)d_in[3];
    const float* ew1  = (const float*)d_in[4];
    const float* eb1  = (const float*)d_in[5];
    const float* eg1  = (const float*)d_in[6];
    const float* ebt1 = (const float*)d_in[7];
    const float* ew2  = (const float*)d_in[8];
    const float* eb2  = (const float*)d_in[9];
    const float* ow1  = (const float*)d_in[10];
    const float* ob1  = (const float*)d_in[11];
    const float* og1  = (const float*)d_in[12];
    const float* obt1 = (const float*)d_in[13];
    const float* ow2  = (const float*)d_in[14];
    const float* ob2  = (const float*)d_in[15];

    int N = in_sizes[0] / 3;
    int M = in_sizes[2] / 3;

    knn_kernel<<<(M + 255) / 256, 256>>>(verts, gverts, M, N);
    mlp_kernel<<<(M + WPB - 1) / WPB, WPB * 32>>>(
        verts, feats, gverts, gfeat,
        ew1, eb1, eg1, ebt1, ew2, eb2,
        ow1, ob1, og1, obt1, ow2, ob2,
        (float*)d_out, M);
}

// round 3
// speedup vs baseline: 1.9080x; 1.9080x over previous
#include <cuda_runtime.h>
#include <math.h>
#include <float.h>

// Problem constants (fixed by the dataset):
//  B=1, N=8192 vertices, M=32*32*32=32768 grid points, Cin=32, Cout=64,
//  K=16 neighbors, edge_in=35 (32 feat + 3 rel_pos), Cprov=96 grid channels.
#define KNN_K   16
#define EDGE_IN 35
#define CIN     32
#define COUT    64
#define CPROV   96
#define MAXM    32768
#define MAXN    8192
#define SCALE   32.0f   // RES / (aabb_max - aabb_min), uniform

#define NB      16      // bins per axis
#define NCELLS  (NB*NB*NB)
#define CSZ_SCALED 2.0f // scaled cell size = 32/16

__device__ int    g_knn[MAXM * KNN_K];
__device__ int    g_cnt[NCELLS];
__device__ int    g_start[NCELLS + 1];
__device__ int    g_cursor[NCELLS];
__device__ float4 g_pts[MAXN];   // scaled (x,y,z,|p|^2), binned order
__device__ int    g_idx[MAXN];   // original vertex index, binned order

__device__ __forceinline__ int cell_of(float x, float y, float z) {
    int cx = min(NB - 1, max(0, (int)(x * (float)NB)));
    int cy = min(NB - 1, max(0, (int)(y * (float)NB)));
    int cz = min(NB - 1, max(0, (int)(z * (float)NB)));
    return (cx << 8) | (cy << 4) | cz;
}

// ---------------------------------------------------------------------------
// Binning pipeline: zero -> count -> scan -> scatter
// ---------------------------------------------------------------------------
__global__ void zero_kernel() {
    int i = blockIdx.x * blockDim.x + threadIdx.x;
    if (i < NCELLS) g_cnt[i] = 0;
}

__global__ void count_kernel(const float* __restrict__ verts, int N) {
    int n = blockIdx.x * blockDim.x + threadIdx.x;
    if (n < N) {
        int c = cell_of(verts[3*n], verts[3*n+1], verts[3*n+2]);
        atomicAdd(&g_cnt[c], 1);
    }
}

__global__ __launch_bounds__(1024) void scan_kernel() {
    __shared__ int s[1024];
    int t = threadIdx.x;
    int base = t * 4;
    int c0 = g_cnt[base], c1 = g_cnt[base+1], c2 = g_cnt[base+2], c3 = g_cnt[base+3];
    int tot = c0 + c1 + c2 + c3;
    s[t] = tot;
    __syncthreads();
    for (int off = 1; off < 1024; off <<= 1) {
        int v = s[t];
        if (t >= off) v += s[t - off];
        __syncthreads();
        s[t] = v;
        __syncthreads();
    }
    int excl = s[t] - tot;
    int p0 = excl, p1 = excl + c0, p2 = p1 + c1, p3 = p2 + c2;
    g_start[base]   = p0; g_cursor[base]   = p0;
    g_start[base+1] = p1; g_cursor[base+1] = p1;
    g_start[base+2] = p2; g_cursor[base+2] = p2;
    g_start[base+3] = p3; g_cursor[base+3] = p3;
    if (t == 1023) g_start[NCELLS] = s[1023];
}

__global__ void scatter_kernel(const float* __restrict__ verts, int N) {
    int n = blockIdx.x * blockDim.x + threadIdx.x;
    if (n < N) {
        float x = verts[3*n], y = verts[3*n+1], z = verts[3*n+2];
        int c = cell_of(x, y, z);
        int pos = atomicAdd(&g_cursor[c], 1);
        float sx = x * SCALE, sy = y * SCALE, sz = z * SCALE;
        g_pts[pos] = make_float4(sx, sy, sz, sx*sx + sy*sy + sz*sz);
        g_idx[pos] = n;
    }
}

// ---------------------------------------------------------------------------
// Binned exact KNN: per grid point, scan Chebyshev shells r=0,1,...;
// after shell r, every unscanned point is >= 2r away (scaled), so stop when
// the current worst of the 16 satisfies wv <= (2r)^2.
// Distance formula identical (same rounding) to the brute-force version.
// ---------------------------------------------------------------------------
__global__ __launch_bounds__(256) void knn_binned_kernel(
    const float* __restrict__ gverts, int M)
{
    int m = blockIdx.x * blockDim.x + threadIdx.x;
    if (m >= M) return;

    float gx = gverts[3*m+0], gy = gverts[3*m+1], gz = gverts[3*m+2];
    float qx = gx * SCALE, qy = gy * SCALE, qz = gz * SCALE;
    float qq  = qx*qx + qy*qy + qz*qz;
    float m2x = -2.f*qx, m2y = -2.f*qy, m2z = -2.f*qz;

    int qcx = min(NB-1, max(0, (int)(gx * (float)NB)));
    int qcy = min(NB-1, max(0, (int)(gy * (float)NB)));
    int qcz = min(NB-1, max(0, (int)(gz * (float)NB)));

    float bv[KNN_K]; int bi[KNN_K];
#pragma unroll
    for (int j = 0; j < KNN_K; j++) { bv[j] = FLT_MAX; bi[j] = 0; }
    float wv = FLT_MAX; int ws = 0;

    auto process_cell = [&](int cx, int cy, int cz) {
        int c = (cx << 8) | (cy << 4) | cz;
        int s = g_start[c], e = g_start[c + 1];
        for (int i = s; i < e; i++) {
            float4 v = g_pts[i];
            float d2 = fmaf(m2x, v.x, fmaf(m2y, v.y, fmaf(m2z, v.z, qq + v.w)));
            if (d2 < wv) {
                int n = g_idx[i];
#pragma unroll
                for (int j = 0; j < KNN_K; j++)
                    if (j == ws) { bv[j] = d2; bi[j] = n; }
                wv = -FLT_MAX;
#pragma unroll
                for (int j = 0; j < KNN_K; j++)
                    if (bv[j] > wv) { wv = bv[j]; ws = j; }
            }
        }
    };

    for (int r = 0; r < NB; r++) {
        int x0 = max(qcx - r, 0), x1 = min(qcx + r, NB - 1);
        int y0 = max(qcy - r, 0), y1 = min(qcy + r, NB - 1);
        int z0 = max(qcz - r, 0), z1 = min(qcz + r, NB - 1);
        for (int cx = x0; cx <= x1; cx++) {
            bool fx = (cx == qcx - r) || (cx == qcx + r);
            for (int cy = y0; cy <= y1; cy++) {
                bool fxy = fx || (cy == qcy - r) || (cy == qcy + r);
                if (fxy) {
                    for (int cz = z0; cz <= z1; cz++) process_cell(cx, cy, cz);
                } else {
                    if (qcz - r >= 0)            process_cell(cx, cy, qcz - r);
                    if (r > 0 && qcz + r <= NB-1) process_cell(cx, cy, qcz + r);
                }
            }
        }
        float bound = CSZ_SCALED * (float)r;
        if (wv <= bound * bound) break;   // all 16 filled and no outside point can beat
    }

#pragma unroll
    for (int j = 0; j < KNN_K; j++) g_knn[m*KNN_K + j] = bi[j];
}

// ---------------------------------------------------------------------------
// Kernel 2: gather + edge MLP + mean + out MLP. One warp per grid point;
// lane handles output channels 2*lane, 2*lane+1 (float2 weight loads).
// Edge layer-2 hoisted past the mean over K (linear commutes with mean).
// Shared reads vectorized to float4 broadcasts to cut LSU wavefronts.
// ---------------------------------------------------------------------------
__device__ __forceinline__ float gelu_tanh(float x) {
    float x3 = x * x * x;
    return 0.5f * x * (1.0f + tanhf(0.7978845608028654f * fmaf(0.044715f, x3, x)));
}

#define WPB 8
__global__ __launch_bounds__(WPB*32) void mlp_kernel(
    const float* __restrict__ verts, const float* __restrict__ feats,
    const float* __restrict__ gverts, const float* __restrict__ gfeat,
    const float* __restrict__ ew1,  const float* __restrict__ eb1,
    const float* __restrict__ eg1,  const float* __restrict__ ebt1,
    const float* __restrict__ ew2,  const float* __restrict__ eb2,
    const float* __restrict__ ow1,  const float* __restrict__ ob1,
    const float* __restrict__ og1,  const float* __restrict__ obt1,
    const float* __restrict__ ow2,  const float* __restrict__ ob2,
    float* __restrict__ out, int M)
{
    __shared__ __align__(16) float sh_e[WPB][KNN_K][36];  // 35 + pad(=0)
    __shared__ __align__(16) float sh_s[WPB][COUT];
    __shared__ __align__(16) float sh_g[WPB][CPROV];

    int w = threadIdx.x >> 5, lane = threadIdx.x & 31;
    int m = blockIdx.x * WPB + w;
    if (m >= M) return;   // uniform per warp

    float gx = gverts[3*m+0], gy = gverts[3*m+1], gz = gverts[3*m+2];

    int myn = 0;
    if (lane < KNN_K) myn = g_knn[m*KNN_K + lane];

    for (int i = lane; i < CPROV; i += 32) sh_g[w][i] = gfeat[m*CPROV + i];

    // stage e_k = [feat(32), rel_pos(3), 0] for all 16 neighbors
    for (int k = 0; k < KNN_K; k++) {
        int n = __shfl_sync(0xffffffffu, myn, k);
        sh_e[w][k][lane] = feats[n*CIN + lane];
        if (lane < 3) {
            float gc = (lane == 0) ? gx : ((lane == 1) ? gy : gz);
            sh_e[w][k][CIN + lane] = verts[n*3 + lane] - gc;
        }
        if (lane == 3) sh_e[w][k][35] = 0.f;
    }
    __syncwarp();

    // ---- edge layer 1: 35 -> 64, register-blocked over K=16 neighbors ----
    float acc0[KNN_K], acc1[KNN_K];
#pragma unroll
    for (int k = 0; k < KNN_K; k++) { acc0[k] = 0.f; acc1[k] = 0.f; }
    const float2* w1 = (const float2*)ew1;
#pragma unroll
    for (int i4 = 0; i4 < 8; i4++) {
        float2 wa = w1[(4*i4+0)*32 + lane];
        float2 wb = w1[(4*i4+1)*32 + lane];
        float2 wc = w1[(4*i4+2)*32 + lane];
        float2 wd = w1[(4*i4+3)*32 + lane];
#pragma unroll
        for (int k = 0; k < KNN_K; k++) {
            float4 ev = ((const float4*)&sh_e[w][k][0])[i4];
            acc0[k] = fmaf(ev.x, wa.x, acc0[k]); acc1[k] = fmaf(ev.x, wa.y, acc1[k]);
            acc0[k] = fmaf(ev.y, wb.x, acc0[k]); acc1[k] = fmaf(ev.y, wb.y, acc1[k]);
            acc0[k] = fmaf(ev.z, wc.x, acc0[k]); acc1[k] = fmaf(ev.z, wc.y, acc1[k]);
            acc0[k] = fmaf(ev.w, wd.x, acc0[k]); acc1[k] = fmaf(ev.w, wd.y, acc1[k]);
        }
    }
    {   // tail rows 32..34 (e[35] == 0, no weight row 35)
        float2 wa = w1[32*32 + lane];
        float2 wb = w1[33*32 + lane];
        float2 wc = w1[34*32 + lane];
#pragma unroll
        for (int k = 0; k < KNN_K; k++) {
            float4 ev = ((const float4*)&sh_e[w][k][0])[8];
            acc0[k] = fmaf(ev.x, wa.x, acc0[k]); acc1[k] = fmaf(ev.x, wa.y, acc1[k]);
            acc0[k] = fmaf(ev.y, wb.x, acc0[k]); acc1[k] = fmaf(ev.y, wb.y, acc1[k]);
            acc0[k] = fmaf(ev.z, wc.x, acc0[k]); acc1[k] = fmaf(ev.z, wc.y, acc1[k]);
        }
    }

    float2 be1 = ((const float2*)eb1)[lane];
    float2 ge1 = ((const float2*)eg1)[lane];
    float2 bt1 = ((const float2*)ebt1)[lane];
    float gm0 = 0.f, gm1 = 0.f;
#pragma unroll
    for (int k = 0; k < KNN_K; k++) {
        float a0 = acc0[k] + be1.x, a1 = acc1[k] + be1.y;
        float s = a0 + a1, s2 = a0*a0 + a1*a1;
#pragma unroll
        for (int o = 16; o; o >>= 1) {
            s  += __shfl_xor_sync(0xffffffffu, s,  o);
            s2 += __shfl_xor_sync(0xffffffffu, s2, o);
        }
        float mean = s * (1.f/COUT);
        float inv  = rsqrtf(s2 * (1.f/COUT) - mean*mean + 1e-5f);
        a0 = (a0 - mean) * inv * ge1.x + bt1.x;
        a1 = (a1 - mean) * inv * ge1.y + bt1.y;
        gm0 += gelu_tanh(a0);
        gm1 += gelu_tanh(a1);
    }
    gm0 *= (1.f/KNN_K); gm1 *= (1.f/KNN_K);

    *(float2*)&sh_s[w][2*lane] = make_float2(gm0, gm1);
    __syncwarp();

    // ---- edge layer 2 (hoisted past mean): 64 -> 64 ----
    float2 be2 = ((const float2*)eb2)[lane];
    float agg0 = be2.x, agg1 = be2.y;
    const float2* w2 = (const float2*)ew2;
    const float4* s4 = (const float4*)sh_s[w];
#pragma unroll
    for (int i4 = 0; i4 < 16; i4++) {
        float4 v = s4[i4];
        float2 wa = w2[(4*i4+0)*32 + lane];
        float2 wb = w2[(4*i4+1)*32 + lane];
        float2 wc = w2[(4*i4+2)*32 + lane];
        float2 wd = w2[(4*i4+3)*32 + lane];
        agg0 = fmaf(v.x, wa.x, agg0); agg1 = fmaf(v.x, wa.y, agg1);
        agg0 = fmaf(v.y, wb.x, agg0); agg1 = fmaf(v.y, wb.y, agg1);
        agg0 = fmaf(v.z, wc.x, agg0); agg1 = fmaf(v.z, wc.y, agg1);
        agg0 = fmaf(v.w, wd.x, agg0); agg1 = fmaf(v.w, wd.y, agg1);
    }
    __syncwarp();
    *(float2*)&sh_s[w][2*lane] = make_float2(agg0, agg1);
    __syncwarp();

    // ---- out layer 1: [agg(64) | grid_feat(96)] -> 64 ----
    float2 bo1 = ((const float2*)ob1)[lane];
    float c0 = bo1.x, c1 = bo1.y;
    const float2* wo1 = (const float2*)ow1;
#pragma unroll
    for (int i4 = 0; i4 < 16; i4++) {
        float4 v = s4[i4];
        float2 wa = wo1[(4*i4+0)*32 + lane];
        float2 wb = wo1[(4*i4+1)*32 + lane];
        float2 wc = wo1[(4*i4+2)*32 + lane];
        float2 wd = wo1[(4*i4+3)*32 + lane];
        c0 = fmaf(v.x, wa.x, c0); c1 = fmaf(v.x, wa.y, c1);
        c0 = fmaf(v.y, wb.x, c0); c1 = fmaf(v.y, wb.y, c1);
        c0 = fmaf(v.z, wc.x, c0); c1 = fmaf(v.z, wc.y, c1);
        c0 = fmaf(v.w, wd.x, c0); c1 = fmaf(v.w, wd.y, c1);
    }
    const float4* g4 = (const float4*)sh_g[w];
#pragma unroll
    for (int i4 = 0; i4 < 24; i4++) {
        float4 v = g4[i4];
        float2 wa = wo1[(COUT + 4*i4+0)*32 + lane];
        float2 wb = wo1[(COUT + 4*i4+1)*32 + lane];
        float2 wc = wo1[(COUT + 4*i4+2)*32 + lane];
        float2 wd = wo1[(COUT + 4*i4+3)*32 + lane];
        c0 = fmaf(v.x, wa.x, c0); c1 = fmaf(v.x, wa.y, c1);
        c0 = fmaf(v.y, wb.x, c0); c1 = fmaf(v.y, wb.y, c1);
        c0 = fmaf(v.z, wc.x, c0); c1 = fmaf(v.z, wc.y, c1);
        c0 = fmaf(v.w, wd.x, c0); c1 = fmaf(v.w, wd.y, c1);
    }
    {
        float s = c0 + c1, s2 = c0*c0 + c1*c1;
#pragma unroll
        for (int o = 16; o; o >>= 1) {
            s  += __shfl_xor_sync(0xffffffffu, s,  o);
            s2 += __shfl_xor_sync(0xffffffffu, s2, o);
        }
        float mean = s * (1.f/COUT);
        float inv  = rsqrtf(s2 * (1.f/COUT) - mean*mean + 1e-5f);
        float2 go = ((const float2*)og1)[lane];
        float2 bo = ((const float2*)obt1)[lane];
        c0 = gelu_tanh((c0 - mean) * inv * go.x + bo.x);
        c1 = gelu_tanh((c1 - mean) * inv * go.y + bo.y);
    }
    __syncwarp();
    *(float2*)&sh_s[w][2*lane] = make_float2(c0, c1);
    __syncwarp();

    // ---- out layer 2: 64 -> 64 ----
    float2 bo2 = ((const float2*)ob2)[lane];
    float o0 = bo2.x, o1 = bo2.y;
    const float2* wo2 = (const float2*)ow2;
#pragma unroll
    for (int i4 = 0; i4 < 16; i4++) {
        float4 v = s4[i4];
        float2 wa = wo2[(4*i4+0)*32 + lane];
        float2 wb = wo2[(4*i4+1)*32 + lane];
        float2 wc = wo2[(4*i4+2)*32 + lane];
        float2 wd = wo2[(4*i4+3)*32 + lane];
        o0 = fmaf(v.x, wa.x, o0); o1 = fmaf(v.x, wa.y, o1);
        o0 = fmaf(v.y, wb.x, o0); o1 = fmaf(v.y, wb.y, o1);
        o0 = fmaf(v.z, wc.x, o0); o1 = fmaf(v.z, wc.y, o1);
        o0 = fmaf(v.w, wd.x, o0); o1 = fmaf(v.w, wd.y, o1);
    }
    ((float2*)out)[m*32 + lane] = make_float2(o0, o1);
}

// ---------------------------------------------------------------------------
// Launch. Input order (metadata.txt / setup_inputs dict order):
//  0 vertices (1,N,3)  1 features (1,N,32)  2 grid_verts (M,3)  3 grid_feat (M,96)
//  4 ew1 (35,64) 5 eb1 6 eg1 7 ebt1 8 ew2 (64,64) 9 eb2
//  10 ow1 (160,64) 11 ob1 12 og1 13 obt1 14 ow2 (64,64) 15 ob2
// Output: (1,32,32,32,64) float32.
// ---------------------------------------------------------------------------
extern "C" void kernel_launch(void* const* d_in, const int* in_sizes, int n_in,
                              void* d_out, int out_size)
{
    const float* verts  = (const float*)d_in[0];
    const float* feats  = (const float*)d_in[1];
    const float* gverts = (const float*)d_in[2];
    const float* gfeat  = (const float*)d_in[3];
    const float* ew1  = (const float*)d_in[4];
    const float* eb1  = (const float*)d_in[5];
    const float* eg1  = (const float*)d_in[6];
    const float* ebt1 = (const float*)d_in[7];
    const float* ew2  = (const float*)d_in[8];
    const float* eb2  = (const float*)d_in[9];
    const float* ow1  = (const float*)d_in[10];
    const float* ob1  = (const float*)d_in[11];
    const float* og1  = (const float*)d_in[12];
    const float* obt1 = (const float*)d_in[13];
    const float* ow2  = (const float*)d_in[14];
    const float* ob2  = (const float*)d_in[15];

    int N = in_sizes[0] / 3;
    int M = in_sizes[2] / 3;

    zero_kernel<<<(NCELLS + 255) / 256, 256>>>();
    count_kernel<<<(N + 255) / 256, 256>>>(verts, N);
    scan_kernel<<<1, 1024>>>();
    scatter_kernel<<<(N + 255) / 256, 256>>>(verts, N);
    knn_binned_kernel<<<(M + 255) / 256, 256>>>(gverts, M);
    mlp_kernel<<<(M + WPB - 1) / WPB, WPB * 32>>>(
        verts, feats, gverts, gfeat,
        ew1, eb1, eg1, ebt1, ew2, eb2,
        ow1, ob1, og1, obt1, ow2, ob2,
        (float*)d_out, M);
}

// round 8
// speedup vs baseline: 2.7757x; 1.4548x over previous
#include <cuda_runtime.h>
#include <math.h>
#include <float.h>

// Problem constants (fixed by the dataset):
//  B=1, N=8192 vertices, M=32*32*32=32768 grid points, Cin=32, Cout=64,
//  K=16 neighbors, edge_in=35 (32 feat + 3 rel_pos), Cprov=96 grid channels.
#define KNN_K   16
#define CIN     32
#define COUT    64
#define CPROV   96
#define MAXM    32768
#define MAXN    8192
#define SCALE   32.0f   // RES / (aabb_max - aabb_min), uniform

#define NB      16      // bins per axis
#define NCELLS  (NB*NB*NB)
#define CSZ_SCALED 2.0f // scaled cell size = 32/16

__device__ int    g_knn[MAXM * KNN_K];
__device__ int    g_cnt[NCELLS];
__device__ int    g_start[NCELLS + 1];
__device__ int    g_cursor[NCELLS];
__device__ float4 g_pts[MAXN];   // scaled (x,y,z,|p|^2), binned order
__device__ int    g_idx[MAXN];   // original vertex index, binned order
__device__ float  g_F1[MAXN * COUT];      // feats@ew1[0:32] + eb1  (per vertex)
__device__ float  g_tab[3 * 32 * COUT];   // per-axis grid-feature @ ow1[64:160]

__device__ __forceinline__ int cell_of(float x, float y, float z) {
    int cx = min(NB - 1, max(0, (int)(x * (float)NB)));
    int cy = min(NB - 1, max(0, (int)(y * (float)NB)));
    int cz = min(NB - 1, max(0, (int)(z * (float)NB)));
    return (cx << 8) | (cy << 4) | cz;
}

// ---------------------------------------------------------------------------
// Binning pipeline: zero -> count -> scan -> scatter
// ---------------------------------------------------------------------------
__global__ void zero_kernel() {
    int i = blockIdx.x * blockDim.x + threadIdx.x;
    if (i < NCELLS) g_cnt[i] = 0;
}

__global__ void count_kernel(const float* __restrict__ verts, int N) {
    int n = blockIdx.x * blockDim.x + threadIdx.x;
    if (n < N) {
        int c = cell_of(verts[3*n], verts[3*n+1], verts[3*n+2]);
        atomicAdd(&g_cnt[c], 1);
    }
}

__global__ __launch_bounds__(1024) void scan_kernel() {
    __shared__ int s[1024];
    int t = threadIdx.x;
    int base = t * 4;
    int c0 = g_cnt[base], c1 = g_cnt[base+1], c2 = g_cnt[base+2], c3 = g_cnt[base+3];
    int tot = c0 + c1 + c2 + c3;
    s[t] = tot;
    __syncthreads();
    for (int off = 1; off < 1024; off <<= 1) {
        int v = s[t];
        if (t >= off) v += s[t - off];
        __syncthreads();
        s[t] = v;
        __syncthreads();
    }
    int excl = s[t] - tot;
    int p0 = excl, p1 = excl + c0, p2 = p1 + c1, p3 = p2 + c2;
    g_start[base]   = p0; g_cursor[base]   = p0;
    g_start[base+1] = p1; g_cursor[base+1] = p1;
    g_start[base+2] = p2; g_cursor[base+2] = p2;
    g_start[base+3] = p3; g_cursor[base+3] = p3;
    if (t == 1023) g_start[NCELLS] = s[1023];
}

__global__ void scatter_kernel(const float* __restrict__ verts, int N) {
    int n = blockIdx.x * blockDim.x + threadIdx.x;
    if (n < N) {
        float x = verts[3*n], y = verts[3*n+1], z = verts[3*n+2];
        int c = cell_of(x, y, z);
        int pos = atomicAdd(&g_cursor[c], 1);
        float sx = x * SCALE, sy = y * SCALE, sz = z * SCALE;
        g_pts[pos] = make_float4(sx, sy, sz, sx*sx + sy*sy + sz*sz);
        g_idx[pos] = n;
    }
}

// ---------------------------------------------------------------------------
// Binned exact KNN: per grid point, scan Chebyshev shells r=0,1,...;
// after shell r, every unscanned point is >= 2r away (scaled), so stop when
// the current worst of the 16 satisfies wv <= (2r)^2.
// ---------------------------------------------------------------------------
__global__ __launch_bounds__(256) void knn_binned_kernel(
    const float* __restrict__ gverts, int M)
{
    int m = blockIdx.x * blockDim.x + threadIdx.x;
    if (m >= M) return;

    float gx = gverts[3*m+0], gy = gverts[3*m+1], gz = gverts[3*m+2];
    float qx = gx * SCALE, qy = gy * SCALE, qz = gz * SCALE;
    float qq  = qx*qx + qy*qy + qz*qz;
    float m2x = -2.f*qx, m2y = -2.f*qy, m2z = -2.f*qz;

    int qcx = min(NB-1, max(0, (int)(gx * (float)NB)));
    int qcy = min(NB-1, max(0, (int)(gy * (float)NB)));
    int qcz = min(NB-1, max(0, (int)(gz * (float)NB)));

    float bv[KNN_K]; int bi[KNN_K];
#pragma unroll
    for (int j = 0; j < KNN_K; j++) { bv[j] = FLT_MAX; bi[j] = 0; }
    float wv = FLT_MAX; int ws = 0;

    auto process_cell = [&](int cx, int cy, int cz) {
        int c = (cx << 8) | (cy << 4) | cz;
        int s = g_start[c], e = g_start[c + 1];
        for (int i = s; i < e; i++) {
            float4 v = g_pts[i];
            float d2 = fmaf(m2x, v.x, fmaf(m2y, v.y, fmaf(m2z, v.z, qq + v.w)));
            if (d2 < wv) {
                int n = g_idx[i];
#pragma unroll
                for (int j = 0; j < KNN_K; j++)
                    if (j == ws) { bv[j] = d2; bi[j] = n; }
                wv = -FLT_MAX;
#pragma unroll
                for (int j = 0; j < KNN_K; j++)
                    if (bv[j] > wv) { wv = bv[j]; ws = j; }
            }
        }
    };

    for (int r = 0; r < NB; r++) {
        int x0 = max(qcx - r, 0), x1 = min(qcx + r, NB - 1);
        int y0 = max(qcy - r, 0), y1 = min(qcy + r, NB - 1);
        int z0 = max(qcz - r, 0), z1 = min(qcz + r, NB - 1);
        for (int cx = x0; cx <= x1; cx++) {
            bool fx = (cx == qcx - r) || (cx == qcx + r);
            for (int cy = y0; cy <= y1; cy++) {
                bool fxy = fx || (cy == qcy - r) || (cy == qcy + r);
                if (fxy) {
                    for (int cz = z0; cz <= z1; cz++) process_cell(cx, cy, cz);
                } else {
                    if (qcz - r >= 0)            process_cell(cx, cy, qcz - r);
                    if (r > 0 && qcz + r <= NB-1) process_cell(cx, cy, qcz + r);
                }
            }
        }
        float bound = CSZ_SCALED * (float)r;
        if (wv <= bound * bound) break;
    }

#pragma unroll
    for (int j = 0; j < KNN_K; j++) g_knn[m*KNN_K + j] = bi[j];
}

// ---------------------------------------------------------------------------
// Precompute F1[n] = feats[n] @ ew1[0:32] + eb1 : (8192, 64).
// One warp per vertex; lane owns channels 2*lane, 2*lane+1.
// ---------------------------------------------------------------------------
__global__ __launch_bounds__(256) void f1_kernel(
    const float* __restrict__ feats, const float* __restrict__ ew1,
    const float* __restrict__ eb1, int N)
{
    int w = threadIdx.x >> 5, lane = threadIdx.x & 31;
    int n = blockIdx.x * 8 + w;
    if (n >= N) return;
    float fl = feats[n*CIN + lane];
    float2 b = ((const float2*)eb1)[lane];
    float a0 = b.x, a1 = b.y;
    const float2* w1 = (const float2*)ew1;
#pragma unroll
    for (int j = 0; j < CIN; j++) {
        float fv = __shfl_sync(0xffffffffu, fl, j);
        float2 wv = w1[j*32 + lane];
        a0 = fmaf(fv, wv.x, a0);
        a1 = fmaf(fv, wv.y, a1);
    }
    ((float2*)g_F1)[n*32 + lane] = make_float2(a0, a1);
}

// ---------------------------------------------------------------------------
// Precompute per-axis grid-feature contributions:
//  tab[a][i][c] = sum_{j<32} gfeat[m_sel(a,i)*96 + 32a + j] * ow1[(64+32a+j)*64 + c]
// where m = ix*1024 + iy*32 + iz (meshgrid 'ij'), so channel block 32a depends
// only on axis-a coordinate. 96 warps total.
// ---------------------------------------------------------------------------
__global__ __launch_bounds__(256) void tab_kernel(
    const float* __restrict__ gfeat, const float* __restrict__ ow1)
{
    int w = threadIdx.x >> 5, lane = threadIdx.x & 31;
    int row = blockIdx.x * 8 + w;          // 0..95
    if (row >= 96) return;
    int a = row >> 5, i = row & 31;
    int m_sel = (a == 0) ? (i << 10) : ((a == 1) ? (i << 5) : i);
    const float* gf = gfeat + m_sel * CPROV + 32 * a;
    const float2* wo = (const float2*)(ow1 + (COUT + 32 * a) * COUT);
    float t0 = 0.f, t1 = 0.f;
#pragma unroll
    for (int j = 0; j < 32; j++) {
        float gv = gf[j];
        float2 wv = wo[j*32 + lane];
        t0 = fmaf(gv, wv.x, t0);
        t1 = fmaf(gv, wv.y, t1);
    }
    ((float2*)g_tab)[row*32 + lane] = make_float2(t0, t1);
}

// ---------------------------------------------------------------------------
// Fused MLP. One warp per 4 grid points (amortizes dense-layer weight loads).
// Edge layer 1 uses precomputed F1[n] + rel_pos @ ew1[32:35].
// Edge layer 2 hoisted past the mean over K. Grid-feature part of out layer 1
// replaced by 3 table lookups (exact separable decomposition).
// ---------------------------------------------------------------------------
__device__ __forceinline__ float gelu_fast(float x) {
    float x3 = x * x * x;
    float g = 1.5957691216057308f * fmaf(0.044715f, x3, x);   // 2*0.79788456*(...)
    float e = __expf(g);
    float t = 1.0f - __fdividef(2.0f, e + 1.0f);              // = tanh(g/2)
    return 0.5f * x * (1.0f + t);
}

#define GPW 4   // grid points per warp
#define WPB 8   // warps per block
__global__ __launch_bounds__(WPB*32) void mlp_kernel(
    const float* __restrict__ verts,  const float* __restrict__ gverts,
    const float* __restrict__ ew1,
    const float* __restrict__ eg1,  const float* __restrict__ ebt1,
    const float* __restrict__ ew2,  const float* __restrict__ eb2,
    const float* __restrict__ ow1,  const float* __restrict__ ob1,
    const float* __restrict__ og1,  const float* __restrict__ obt1,
    const float* __restrict__ ow2,  const float* __restrict__ ob2,
    float* __restrict__ out, int M)
{
    __shared__ __align__(16) float sh_a[WPB][GPW][COUT];  // staging A
    __shared__ __align__(16) float sh_b[WPB][GPW][COUT];  // staging B

    int w = threadIdx.x >> 5, lane = threadIdx.x & 31;
    int mbase = (blockIdx.x * WPB + w) * GPW;
    if (mbase >= M) return;   // uniform per warp

    // preload small per-lane constants
    float2 wpx = ((const float2*)ew1)[32*32 + lane];
    float2 wpy = ((const float2*)ew1)[33*32 + lane];
    float2 wpz = ((const float2*)ew1)[34*32 + lane];
    float2 ge1 = ((const float2*)eg1)[lane];
    float2 bt1 = ((const float2*)ebt1)[lane];
    const float2* F1 = (const float2*)g_F1;

    // ---- phase 1: per point, edge layer1 + LN + GELU + mean over K ----
#pragma unroll
    for (int p = 0; p < GPW; p++) {
        int m = mbase + p;
        float gx = gverts[3*m+0], gy = gverts[3*m+1], gz = gverts[3*m+2];
        int myn = 0;
        if (lane < KNN_K) myn = g_knn[m*KNN_K + lane];
        float gm0 = 0.f, gm1 = 0.f;
#pragma unroll
        for (int k = 0; k < KNN_K; k++) {
            int n = __shfl_sync(0xffffffffu, myn, k);
            float2 f = F1[n*32 + lane];
            float vc = (lane < 3) ? verts[n*3 + lane] : 0.f;
            float rx = __shfl_sync(0xffffffffu, vc, 0) - gx;
            float ry = __shfl_sync(0xffffffffu, vc, 1) - gy;
            float rz = __shfl_sync(0xffffffffu, vc, 2) - gz;
            float a0 = fmaf(rx, wpx.x, fmaf(ry, wpy.x, fmaf(rz, wpz.x, f.x)));
            float a1 = fmaf(rx, wpx.y, fmaf(ry, wpy.y, fmaf(rz, wpz.y, f.y)));
            float s = a0 + a1, s2 = a0*a0 + a1*a1;
#pragma unroll
            for (int o = 16; o; o >>= 1) {
                s  += __shfl_xor_sync(0xffffffffu, s,  o);
                s2 += __shfl_xor_sync(0xffffffffu, s2, o);
            }
            float mean = s * (1.f/COUT);
            float inv  = rsqrtf(s2 * (1.f/COUT) - mean*mean + 1e-5f);
            a0 = (a0 - mean) * inv * ge1.x + bt1.x;
            a1 = (a1 - mean) * inv * ge1.y + bt1.y;
            gm0 += gelu_fast(a0);
            gm1 += gelu_fast(a1);
        }
        *(float2*)&sh_a[w][p][2*lane] = make_float2(gm0 * (1.f/KNN_K), gm1 * (1.f/KNN_K));
    }
    __syncwarp();

    // ---- phase 2: edge layer 2 (hoisted past mean): 64 -> 64, x4 points ----
    {
        float2 be2 = ((const float2*)eb2)[lane];
        float a0[GPW], a1[GPW];
#pragma unroll
        for (int p = 0; p < GPW; p++) { a0[p] = be2.x; a1[p] = be2.y; }
        const float2* w2 = (const float2*)ew2;
#pragma unroll
        for (int i4 = 0; i4 < 16; i4++) {
            float2 wa = w2[(4*i4+0)*32 + lane];
            float2 wb = w2[(4*i4+1)*32 + lane];
            float2 wc = w2[(4*i4+2)*32 + lane];
            float2 wd = w2[(4*i4+3)*32 + lane];
#pragma unroll
            for (int p = 0; p < GPW; p++) {
                float4 v = ((const float4*)sh_a[w][p])[i4];
                a0[p] = fmaf(v.x, wa.x, a0[p]); a1[p] = fmaf(v.x, wa.y, a1[p]);
                a0[p] = fmaf(v.y, wb.x, a0[p]); a1[p] = fmaf(v.y, wb.y, a1[p]);
                a0[p] = fmaf(v.z, wc.x, a0[p]); a1[p] = fmaf(v.z, wc.y, a1[p]);
                a0[p] = fmaf(v.w, wd.x, a0[p]); a1[p] = fmaf(v.w, wd.y, a1[p]);
            }
        }
        __syncwarp();
#pragma unroll
        for (int p = 0; p < GPW; p++)
            *(float2*)&sh_b[w][p][2*lane] = make_float2(a0[p], a1[p]);
        __syncwarp();
    }

    // ---- phase 3: out layer 1: agg(64)@ow1[0:64] + table(ix,iy,iz), LN, GELU ----
    {
        float2 bo1 = ((const float2*)ob1)[lane];
        float c0[GPW], c1[GPW];
#pragma unroll
        for (int p = 0; p < GPW; p++) { c0[p] = bo1.x; c1[p] = bo1.y; }
        const float2* wo1 = (const float2*)ow1;
#pragma unroll
        for (int i4 = 0; i4 < 16; i4++) {
            float2 wa = wo1[(4*i4+0)*32 + lane];
            float2 wb = wo1[(4*i4+1)*32 + lane];
            float2 wc = wo1[(4*i4+2)*32 + lane];
            float2 wd = wo1[(4*i4+3)*32 + lane];
#pragma unroll
            for (int p = 0; p < GPW; p++) {
                float4 v = ((const float4*)sh_b[w][p])[i4];
                c0[p] = fmaf(v.x, wa.x, c0[p]); c1[p] = fmaf(v.x, wa.y, c1[p]);
                c0[p] = fmaf(v.y, wb.x, c0[p]); c1[p] = fmaf(v.y, wb.y, c1[p]);
                c0[p] = fmaf(v.z, wc.x, c0[p]); c1[p] = fmaf(v.z, wc.y, c1[p]);
                c0[p] = fmaf(v.w, wd.x, c0[p]); c1[p] = fmaf(v.w, wd.y, c1[p]);
            }
        }
        const float2* tab = (const float2*)g_tab;
        float2 go = ((const float2*)og1)[lane];
        float2 bo = ((const float2*)obt1)[lane];
#pragma unroll
        for (int p = 0; p < GPW; p++) {
            int m = mbase + p;
            int ix = m >> 10, iy = (m >> 5) & 31, iz = m & 31;
            float2 tx = tab[(0*32 + ix)*32 + lane];
            float2 ty = tab[(1*32 + iy)*32 + lane];
            float2 tz = tab[(2*32 + iz)*32 + lane];
            float a0 = c0[p] + tx.x + ty.x + tz.x;
            float a1 = c1[p] + tx.y + ty.y + tz.y;
            float s = a0 + a1, s2 = a0*a0 + a1*a1;
#pragma unroll
            for (int o = 16; o; o >>= 1) {
                s  += __shfl_xor_sync(0xffffffffu, s,  o);
                s2 += __shfl_xor_sync(0xffffffffu, s2, o);
            }
            float mean = s * (1.f/COUT);
            float inv  = rsqrtf(s2 * (1.f/COUT) - mean*mean + 1e-5f);
            a0 = (a0 - mean) * inv * go.x + bo.x;
            a1 = (a1 - mean) * inv * go.y + bo.y;
            *(float2*)&sh_a[w][p][2*lane] = make_float2(gelu_fast(a0), gelu_fast(a1));
        }
        __syncwarp();
    }

    // ---- phase 4: out layer 2: 64 -> 64, x4 points, store ----
    {
        float2 bo2 = ((const float2*)ob2)[lane];
        float o0[GPW], o1[GPW];
#pragma unroll
        for (int p = 0; p < GPW; p++) { o0[p] = bo2.x; o1[p] = bo2.y; }
        const float2* wo2 = (const float2*)ow2;
#pragma unroll
        for (int i4 = 0; i4 < 16; i4++) {
            float2 wa = wo2[(4*i4+0)*32 + lane];
            float2 wb = wo2[(4*i4+1)*32 + lane];
            float2 wc = wo2[(4*i4+2)*32 + lane];
            float2 wd = wo2[(4*i4+3)*32 + lane];
#pragma unroll
            for (int p = 0; p < GPW; p++) {
                float4 v = ((const float4*)sh_a[w][p])[i4];
                o0[p] = fmaf(v.x, wa.x, o0[p]); o1[p] = fmaf(v.x, wa.y, o1[p]);
                o0[p] = fmaf(v.y, wb.x, o0[p]); o1[p] = fmaf(v.y, wb.y, o1[p]);
                o0[p] = fmaf(v.z, wc.x, o0[p]); o1[p] = fmaf(v.z, wc.y, o1[p]);
                o0[p] = fmaf(v.w, wd.x, o0[p]); o1[p] = fmaf(v.w, wd.y, o1[p]);
            }
        }
#pragma unroll
        for (int p = 0; p < GPW; p++)
            ((float2*)out)[(mbase + p)*32 + lane] = make_float2(o0[p], o1[p]);
    }
}

// ---------------------------------------------------------------------------
// Launch. Input order:
//  0 vertices (1,N,3)  1 features (1,N,32)  2 grid_verts (M,3)  3 grid_feat (M,96)
//  4 ew1 (35,64) 5 eb1 6 eg1 7 ebt1 8 ew2 (64,64) 9 eb2
//  10 ow1 (160,64) 11 ob1 12 og1 13 obt1 14 ow2 (64,64) 15 ob2
// Output: (1,32,32,32,64) float32.
// ---------------------------------------------------------------------------
extern "C" void kernel_launch(void* const* d_in, const int* in_sizes, int n_in,
                              void* d_out, int out_size)
{
    const float* verts  = (const float*)d_in[0];
    const float* feats  = (const float*)d_in[1];
    const float* gverts = (const float*)d_in[2];
    const float* gfeat  = (const float*)d_in[3];
    const float* ew1  = (const float*)d_in[4];
    const float* eb1  = (const float*)d_in[5];
    const float* eg1  = (const float*)d_in[6];
    const float* ebt1 = (const float*)d_in[7];
    const float* ew2  = (const float*)d_in[8];
    const float* eb2  = (const float*)d_in[9];
    const float* ow1  = (const float*)d_in[10];
    const float* ob1  = (const float*)d_in[11];
    const float* og1  = (const float*)d_in[12];
    const float* obt1 = (const float*)d_in[13];
    const float* ow2  = (const float*)d_in[14];
    const float* ob2  = (const float*)d_in[15];

    int N = in_sizes[0] / 3;
    int M = in_sizes[2] / 3;

    zero_kernel<<<(NCELLS + 255) / 256, 256>>>();
    count_kernel<<<(N + 255) / 256, 256>>>(verts, N);
    scan_kernel<<<1, 1024>>>();
    scatter_kernel<<<(N + 255) / 256, 256>>>(verts, N);
    knn_binned_kernel<<<(M + 255) / 256, 256>>>(gverts, M);
    f1_kernel<<<(N + 7) / 8, 256>>>(feats, ew1, eb1, N);
    tab_kernel<<<12, 256>>>(gfeat, ow1);
    mlp_kernel<<<(M + WPB*GPW - 1) / (WPB*GPW), WPB * 32>>>(
        verts, gverts, ew1,
        eg1, ebt1, ew2, eb2,
        ow1, ob1, og1, obt1, ow2, ob2,
        (float*)d_out, M);
}

// round 9
// speedup vs baseline: 3.6667x; 1.3210x over previous
#include <cuda_runtime.h>
#include <math.h>
#include <float.h>

// Problem constants (fixed by the dataset):
//  B=1, N=8192 vertices, M=32*32*32=32768 grid points, Cin=32, Cout=64,
//  K=16 neighbors, edge_in=35 (32 feat + 3 rel_pos), Cprov=96 grid channels.
#define KNN_K   16
#define CIN     32
#define COUT    64
#define CPROV   96
#define MAXM    32768
#define MAXN    8192
#define SCALE   32.0f   // RES / (aabb_max - aabb_min), uniform

#define NB      16      // bins per axis
#define NCELLS  (NB*NB*NB)
#define CSZ_SCALED 2.0f // scaled cell size = 32/16

__device__ int    g_knn[MAXM * KNN_K];
__device__ int    g_cnt[NCELLS];
__device__ int    g_start[NCELLS + 1];
__device__ int    g_cursor[NCELLS];
__device__ float4 g_pts[MAXN];   // scaled (x,y,z,|p|^2), binned order
__device__ int    g_idx[MAXN];   // original vertex index, binned order
__device__ float  g_F1[MAXN * COUT];      // feats@ew1[0:32] + eb1  (per vertex)
__device__ float  g_tab[3 * 32 * COUT];   // per-axis grid-feature @ ow1[64:160]

__device__ __forceinline__ int cell_of(float x, float y, float z) {
    int cx = min(NB - 1, max(0, (int)(x * (float)NB)));
    int cy = min(NB - 1, max(0, (int)(y * (float)NB)));
    int cz = min(NB - 1, max(0, (int)(z * (float)NB)));
    return (cx << 8) | (cy << 4) | cz;
}

// ---------------------------------------------------------------------------
// Binning pipeline: zero -> count -> scan -> scatter
// ---------------------------------------------------------------------------
__global__ void zero_kernel() {
    int i = blockIdx.x * blockDim.x + threadIdx.x;
    if (i < NCELLS) g_cnt[i] = 0;
}

__global__ void count_kernel(const float* __restrict__ verts, int N) {
    int n = blockIdx.x * blockDim.x + threadIdx.x;
    if (n < N) {
        int c = cell_of(verts[3*n], verts[3*n+1], verts[3*n+2]);
        atomicAdd(&g_cnt[c], 1);
    }
}

__global__ __launch_bounds__(1024) void scan_kernel() {
    __shared__ int s[1024];
    int t = threadIdx.x;
    int base = t * 4;
    int c0 = g_cnt[base], c1 = g_cnt[base+1], c2 = g_cnt[base+2], c3 = g_cnt[base+3];
    int tot = c0 + c1 + c2 + c3;
    s[t] = tot;
    __syncthreads();
    for (int off = 1; off < 1024; off <<= 1) {
        int v = s[t];
        if (t >= off) v += s[t - off];
        __syncthreads();
        s[t] = v;
        __syncthreads();
    }
    int excl = s[t] - tot;
    int p0 = excl, p1 = excl + c0, p2 = p1 + c1, p3 = p2 + c2;
    g_start[base]   = p0; g_cursor[base]   = p0;
    g_start[base+1] = p1; g_cursor[base+1] = p1;
    g_start[base+2] = p2; g_cursor[base+2] = p2;
    g_start[base+3] = p3; g_cursor[base+3] = p3;
    if (t == 1023) g_start[NCELLS] = s[1023];
}

__global__ void scatter_kernel(const float* __restrict__ verts, int N) {
    int n = blockIdx.x * blockDim.x + threadIdx.x;
    if (n < N) {
        float x = verts[3*n], y = verts[3*n+1], z = verts[3*n+2];
        int c = cell_of(x, y, z);
        int pos = atomicAdd(&g_cursor[c], 1);
        float sx = x * SCALE, sy = y * SCALE, sz = z * SCALE;
        g_pts[pos] = make_float4(sx, sy, sz, sx*sx + sy*sy + sz*sz);
        g_idx[pos] = n;
    }
}

// ---------------------------------------------------------------------------
// Binned exact KNN, warp-coherent mapping + contiguous z-spans.
//  - Thread->point swizzle: each warp covers a 4x4x2 point chunk so all lanes'
//    home cells (and hence shell walks) nearly coincide -> lockstep branches,
//    broadcast loads.
//  - Cells are linearized (cx<<8)|(cy<<4)|cz and g_pts is cell-sorted, so a
//    z-run of cells is ONE contiguous candidate range.
//  - Shell stop: after shell r every unscanned point is >= 2r away (scaled).
// ---------------------------------------------------------------------------
__global__ __launch_bounds__(256) void knn_binned_kernel(
    const float* __restrict__ gverts, int M)
{
    int b = blockIdx.x;
    int bx = b & 3, by = (b >> 2) & 3, bz = b >> 4;          // 4 x 4 x 8 blocks
    int w = threadIdx.x >> 5, l = threadIdx.x & 31;
    int ix = bx*8 + ((w & 1) << 2) + (l & 3);                // 8x8x4 per block
    int iy = by*8 + (((w >> 1) & 1) << 2) + ((l >> 2) & 3);  // warp: 4x4x2
    int iz = bz*4 + (((w >> 2) & 1) << 1) + (l >> 4);
    int m = (ix << 10) | (iy << 5) | iz;
    if (m >= M) return;

    float gx = gverts[3*m+0], gy = gverts[3*m+1], gz = gverts[3*m+2];
    float qx = gx * SCALE, qy = gy * SCALE, qz = gz * SCALE;
    float qq  = qx*qx + qy*qy + qz*qz;
    float m2x = -2.f*qx, m2y = -2.f*qy, m2z = -2.f*qz;

    int qcx = min(NB-1, max(0, (int)(gx * (float)NB)));
    int qcy = min(NB-1, max(0, (int)(gy * (float)NB)));
    int qcz = min(NB-1, max(0, (int)(gz * (float)NB)));

    float bv[KNN_K]; int bi[KNN_K];
#pragma unroll
    for (int j = 0; j < KNN_K; j++) { bv[j] = FLT_MAX; bi[j] = 0; }
    float wv = FLT_MAX; int ws = 0;

    // candidates for cells (cx,cy,[zlo..zhi]) are one contiguous range
    auto process_span = [&](int cx, int cy, int zlo, int zhi) {
        int cbase = (cx << 8) | (cy << 4);
        int s = g_start[cbase | zlo], e = g_start[(cbase | zhi) + 1];
        for (int i = s; i < e; i++) {
            float4 v = g_pts[i];
            float d2 = fmaf(m2x, v.x, fmaf(m2y, v.y, fmaf(m2z, v.z, qq + v.w)));
            if (d2 < wv) {
                int n = g_idx[i];
#pragma unroll
                for (int j = 0; j < KNN_K; j++)
                    if (j == ws) { bv[j] = d2; bi[j] = n; }
                wv = -FLT_MAX;
#pragma unroll
                for (int j = 0; j < KNN_K; j++)
                    if (bv[j] > wv) { wv = bv[j]; ws = j; }
            }
        }
    };

    for (int r = 0; r < NB; r++) {
        int x0 = max(qcx - r, 0), x1 = min(qcx + r, NB - 1);
        int y0 = max(qcy - r, 0), y1 = min(qcy + r, NB - 1);
        int z0 = max(qcz - r, 0), z1 = min(qcz + r, NB - 1);
        for (int cx = x0; cx <= x1; cx++) {
            bool fx = (cx == qcx - r) || (cx == qcx + r);
            for (int cy = y0; cy <= y1; cy++) {
                bool fxy = fx || (cy == qcy - r) || (cy == qcy + r);
                if (fxy) {
                    process_span(cx, cy, z0, z1);
                } else {
                    if (qcz - r >= 0)             process_span(cx, cy, qcz - r, qcz - r);
                    if (r > 0 && qcz + r <= NB-1) process_span(cx, cy, qcz + r, qcz + r);
                }
            }
        }
        float bound = CSZ_SCALED * (float)r;
        if (wv <= bound * bound) break;
    }

#pragma unroll
    for (int j = 0; j < KNN_K; j++) g_knn[m*KNN_K + j] = bi[j];
}

// ---------------------------------------------------------------------------
// Precompute F1[n] = feats[n] @ ew1[0:32] + eb1 : (8192, 64).
// ---------------------------------------------------------------------------
__global__ __launch_bounds__(256) void f1_kernel(
    const float* __restrict__ feats, const float* __restrict__ ew1,
    const float* __restrict__ eb1, int N)
{
    int w = threadIdx.x >> 5, lane = threadIdx.x & 31;
    int n = blockIdx.x * 8 + w;
    if (n >= N) return;
    float fl = feats[n*CIN + lane];
    float2 b = ((const float2*)eb1)[lane];
    float a0 = b.x, a1 = b.y;
    const float2* w1 = (const float2*)ew1;
#pragma unroll
    for (int j = 0; j < CIN; j++) {
        float fv = __shfl_sync(0xffffffffu, fl, j);
        float2 wv = w1[j*32 + lane];
        a0 = fmaf(fv, wv.x, a0);
        a1 = fmaf(fv, wv.y, a1);
    }
    ((float2*)g_F1)[n*32 + lane] = make_float2(a0, a1);
}

// ---------------------------------------------------------------------------
// Precompute per-axis grid-feature contributions (exact separable split of
// gfeat[m] @ ow1[64:160] since channel block 32a depends only on axis a).
// ---------------------------------------------------------------------------
__global__ __launch_bounds__(256) void tab_kernel(
    const float* __restrict__ gfeat, const float* __restrict__ ow1)
{
    int w = threadIdx.x >> 5, lane = threadIdx.x & 31;
    int row = blockIdx.x * 8 + w;          // 0..95
    if (row >= 96) return;
    int a = row >> 5, i = row & 31;
    int m_sel = (a == 0) ? (i << 10) : ((a == 1) ? (i << 5) : i);
    const float* gf = gfeat + m_sel * CPROV + 32 * a;
    const float2* wo = (const float2*)(ow1 + (COUT + 32 * a) * COUT);
    float t0 = 0.f, t1 = 0.f;
#pragma unroll
    for (int j = 0; j < 32; j++) {
        float gv = gf[j];
        float2 wv = wo[j*32 + lane];
        t0 = fmaf(gv, wv.x, t0);
        t1 = fmaf(gv, wv.y, t1);
    }
    ((float2*)g_tab)[row*32 + lane] = make_float2(t0, t1);
}

// ---------------------------------------------------------------------------
// Fused MLP. One warp per 4 grid points (amortizes dense-layer weight loads).
// Edge layer 1 uses precomputed F1[n] + rel_pos @ ew1[32:35].
// Edge layer 2 hoisted past the mean over K. Grid-feature part of out layer 1
// replaced by 3 table lookups (exact separable decomposition).
// ---------------------------------------------------------------------------
__device__ __forceinline__ float gelu_fast(float x) {
    float x3 = x * x * x;
    float g = 1.5957691216057308f * fmaf(0.044715f, x3, x);   // 2*0.79788456*(...)
    float e = __expf(g);
    float t = 1.0f - __fdividef(2.0f, e + 1.0f);              // = tanh(g/2)
    return 0.5f * x * (1.0f + t);
}

#define GPW 4   // grid points per warp
#define WPB 8   // warps per block
__global__ __launch_bounds__(WPB*32) void mlp_kernel(
    const float* __restrict__ verts,  const float* __restrict__ gverts,
    const float* __restrict__ ew1,
    const float* __restrict__ eg1,  const float* __restrict__ ebt1,
    const float* __restrict__ ew2,  const float* __restrict__ eb2,
    const float* __restrict__ ow1,  const float* __restrict__ ob1,
    const float* __restrict__ og1,  const float* __restrict__ obt1,
    const float* __restrict__ ow2,  const float* __restrict__ ob2,
    float* __restrict__ out, int M)
{
    __shared__ __align__(16) float sh_a[WPB][GPW][COUT];  // staging A
    __shared__ __align__(16) float sh_b[WPB][GPW][COUT];  // staging B

    int w = threadIdx.x >> 5, lane = threadIdx.x & 31;
    int mbase = (blockIdx.x * WPB + w) * GPW;
    if (mbase >= M) return;   // uniform per warp

    // preload small per-lane constants
    float2 wpx = ((const float2*)ew1)[32*32 + lane];
    float2 wpy = ((const float2*)ew1)[33*32 + lane];
    float2 wpz = ((const float2*)ew1)[34*32 + lane];
    float2 ge1 = ((const float2*)eg1)[lane];
    float2 bt1 = ((const float2*)ebt1)[lane];
    const float2* F1 = (const float2*)g_F1;

    // ---- phase 1: per point, edge layer1 + LN + GELU + mean over K ----
#pragma unroll
    for (int p = 0; p < GPW; p++) {
        int m = mbase + p;
        float gx = gverts[3*m+0], gy = gverts[3*m+1], gz = gverts[3*m+2];
        int myn = 0;
        if (lane < KNN_K) myn = g_knn[m*KNN_K + lane];
        float gm0 = 0.f, gm1 = 0.f;
#pragma unroll
        for (int k = 0; k < KNN_K; k++) {
            int n = __shfl_sync(0xffffffffu, myn, k);
            float2 f = F1[n*32 + lane];
            float vc = (lane < 3) ? verts[n*3 + lane] : 0.f;
            float rx = __shfl_sync(0xffffffffu, vc, 0) - gx;
            float ry = __shfl_sync(0xffffffffu, vc, 1) - gy;
            float rz = __shfl_sync(0xffffffffu, vc, 2) - gz;
            float a0 = fmaf(rx, wpx.x, fmaf(ry, wpy.x, fmaf(rz, wpz.x, f.x)));
            float a1 = fmaf(rx, wpx.y, fmaf(ry, wpy.y, fmaf(rz, wpz.y, f.y)));
            float s = a0 + a1, s2 = a0*a0 + a1*a1;
#pragma unroll
            for (int o = 16; o; o >>= 1) {
                s  += __shfl_xor_sync(0xffffffffu, s,  o);
                s2 += __shfl_xor_sync(0xffffffffu, s2, o);
            }
            float mean = s * (1.f/COUT);
            float inv  = rsqrtf(s2 * (1.f/COUT) - mean*mean + 1e-5f);
            a0 = (a0 - mean) * inv * ge1.x + bt1.x;
            a1 = (a1 - mean) * inv * ge1.y + bt1.y;
            gm0 += gelu_fast(a0);
            gm1 += gelu_fast(a1);
        }
        *(float2*)&sh_a[w][p][2*lane] = make_float2(gm0 * (1.f/KNN_K), gm1 * (1.f/KNN_K));
    }
    __syncwarp();

    // ---- phase 2: edge layer 2 (hoisted past mean): 64 -> 64, x4 points ----
    {
        float2 be2 = ((const float2*)eb2)[lane];
        float a0[GPW], a1[GPW];
#pragma unroll
        for (int p = 0; p < GPW; p++) { a0[p] = be2.x; a1[p] = be2.y; }
        const float2* w2 = (const float2*)ew2;
#pragma unroll
        for (int i4 = 0; i4 < 16; i4++) {
            float2 wa = w2[(4*i4+0)*32 + lane];
            float2 wb = w2[(4*i4+1)*32 + lane];
            float2 wc = w2[(4*i4+2)*32 + lane];
            float2 wd = w2[(4*i4+3)*32 + lane];
#pragma unroll
            for (int p = 0; p < GPW; p++) {
                float4 v = ((const float4*)sh_a[w][p])[i4];
                a0[p] = fmaf(v.x, wa.x, a0[p]); a1[p] = fmaf(v.x, wa.y, a1[p]);
                a0[p] = fmaf(v.y, wb.x, a0[p]); a1[p] = fmaf(v.y, wb.y, a1[p]);
                a0[p] = fmaf(v.z, wc.x, a0[p]); a1[p] = fmaf(v.z, wc.y, a1[p]);
                a0[p] = fmaf(v.w, wd.x, a0[p]); a1[p] = fmaf(v.w, wd.y, a1[p]);
            }
        }
        __syncwarp();
#pragma unroll
        for (int p = 0; p < GPW; p++)
            *(float2*)&sh_b[w][p][2*lane] = make_float2(a0[p], a1[p]);
        __syncwarp();
    }

    // ---- phase 3: out layer 1: agg(64)@ow1[0:64] + table(ix,iy,iz), LN, GELU ----
    {
        float2 bo1 = ((const float2*)ob1)[lane];
        float c0[GPW], c1[GPW];
#pragma unroll
        for (int p = 0; p < GPW; p++) { c0[p] = bo1.x; c1[p] = bo1.y; }
        const float2* wo1 = (const float2*)ow1;
#pragma unroll
        for (int i4 = 0; i4 < 16; i4++) {
            float2 wa = wo1[(4*i4+0)*32 + lane];
            float2 wb = wo1[(4*i4+1)*32 + lane];
            float2 wc = wo1[(4*i4+2)*32 + lane];
            float2 wd = wo1[(4*i4+3)*32 + lane];
#pragma unroll
            for (int p = 0; p < GPW; p++) {
                float4 v = ((const float4*)sh_b[w][p])[i4];
                c0[p] = fmaf(v.x, wa.x, c0[p]); c1[p] = fmaf(v.x, wa.y, c1[p]);
                c0[p] = fmaf(v.y, wb.x, c0[p]); c1[p] = fmaf(v.y, wb.y, c1[p]);
                c0[p] = fmaf(v.z, wc.x, c0[p]); c1[p] = fmaf(v.z, wc.y, c1[p]);
                c0[p] = fmaf(v.w, wd.x, c0[p]); c1[p] = fmaf(v.w, wd.y, c1[p]);
            }
        }
        const float2* tab = (const float2*)g_tab;
        float2 go = ((const float2*)og1)[lane];
        float2 bo = ((const float2*)obt1)[lane];
#pragma unroll
        for (int p = 0; p < GPW; p++) {
            int m = mbase + p;
            int ix = m >> 10, iy = (m >> 5) & 31, iz = m & 31;
            float2 tx = tab[(0*32 + ix)*32 + lane];
            float2 ty = tab[(1*32 + iy)*32 + lane];
            float2 tz = tab[(2*32 + iz)*32 + lane];
            float a0 = c0[p] + tx.x + ty.x + tz.x;
            float a1 = c1[p] + tx.y + ty.y + tz.y;
            float s = a0 + a1, s2 = a0*a0 + a1*a1;
#pragma unroll
            for (int o = 16; o; o >>= 1) {
                s  += __shfl_xor_sync(0xffffffffu, s,  o);
                s2 += __shfl_xor_sync(0xffffffffu, s2, o);
            }
            float mean = s * (1.f/COUT);
            float inv  = rsqrtf(s2 * (1.f/COUT) - mean*mean + 1e-5f);
            a0 = (a0 - mean) * inv * go.x + bo.x;
            a1 = (a1 - mean) * inv * go.y + bo.y;
            *(float2*)&sh_a[w][p][2*lane] = make_float2(gelu_fast(a0), gelu_fast(a1));
        }
        __syncwarp();
    }

    // ---- phase 4: out layer 2: 64 -> 64, x4 points, store ----
    {
        float2 bo2 = ((const float2*)ob2)[lane];
        float o0[GPW], o1[GPW];
#pragma unroll
        for (int p = 0; p < GPW; p++) { o0[p] = bo2.x; o1[p] = bo2.y; }
        const float2* wo2 = (const float2*)ow2;
#pragma unroll
        for (int i4 = 0; i4 < 16; i4++) {
            float2 wa = wo2[(4*i4+0)*32 + lane];
            float2 wb = wo2[(4*i4+1)*32 + lane];
            float2 wc = wo2[(4*i4+2)*32 + lane];
            float2 wd = wo2[(4*i4+3)*32 + lane];
#pragma unroll
            for (int p = 0; p < GPW; p++) {
                float4 v = ((const float4*)sh_a[w][p])[i4];
                o0[p] = fmaf(v.x, wa.x, o0[p]); o1[p] = fmaf(v.x, wa.y, o1[p]);
                o0[p] = fmaf(v.y, wb.x, o0[p]); o1[p] = fmaf(v.y, wb.y, o1[p]);
                o0[p] = fmaf(v.z, wc.x, o0[p]); o1[p] = fmaf(v.z, wc.y, o1[p]);
                o0[p] = fmaf(v.w, wd.x, o0[p]); o1[p] = fmaf(v.w, wd.y, o1[p]);
            }
        }
#pragma unroll
        for (int p = 0; p < GPW; p++)
            ((float2*)out)[(mbase + p)*32 + lane] = make_float2(o0[p], o1[p]);
    }
}

// ---------------------------------------------------------------------------
// Launch. Input order:
//  0 vertices (1,N,3)  1 features (1,N,32)  2 grid_verts (M,3)  3 grid_feat (M,96)
//  4 ew1 (35,64) 5 eb1 6 eg1 7 ebt1 8 ew2 (64,64) 9 eb2
//  10 ow1 (160,64) 11 ob1 12 og1 13 obt1 14 ow2 (64,64) 15 ob2
// Output: (1,32,32,32,64) float32.
// ---------------------------------------------------------------------------
extern "C" void kernel_launch(void* const* d_in, const int* in_sizes, int n_in,
                              void* d_out, int out_size)
{
    const float* verts  = (const float*)d_in[0];
    const float* feats  = (const float*)d_in[1];
    const float* gverts = (const float*)d_in[2];
    const float* gfeat  = (const float*)d_in[3];
    const float* ew1  = (const float*)d_in[4];
    const float* eb1  = (const float*)d_in[5];
    const float* eg1  = (const float*)d_in[6];
    const float* ebt1 = (const float*)d_in[7];
    const float* ew2  = (const float*)d_in[8];
    const float* eb2  = (const float*)d_in[9];
    const float* ow1  = (const float*)d_in[10];
    const float* ob1  = (const float*)d_in[11];
    const float* og1  = (const float*)d_in[12];
    const float* obt1 = (const float*)d_in[13];
    const float* ow2  = (const float*)d_in[14];
    const float* ob2  = (const float*)d_in[15];

    int N = in_sizes[0] / 3;
    int M = in_sizes[2] / 3;

    zero_kernel<<<(NCELLS + 255) / 256, 256>>>();
    count_kernel<<<(N + 255) / 256, 256>>>(verts, N);
    scan_kernel<<<1, 1024>>>();
    scatter_kernel<<<(N + 255) / 256, 256>>>(verts, N);
    knn_binned_kernel<<<128, 256>>>(gverts, M);
    f1_kernel<<<(N + 7) / 8, 256>>>(feats, ew1, eb1, N);
    tab_kernel<<<12, 256>>>(gfeat, ow1);
    mlp_kernel<<<(M + WPB*GPW - 1) / (WPB*GPW), WPB * 32>>>(
        verts, gverts, ew1,
        eg1, ebt1, ew2, eb2,
        ow1, ob1, og1, obt1, ow2, ob2,
        (float*)d_out, M);
}

// round 12
// speedup vs baseline: 3.8785x; 1.0578x over previous
#include <cuda_runtime.h>
#include <math.h>
#include <float.h>

// Problem constants (fixed by the dataset):
//  B=1, N=8192 vertices, M=32*32*32=32768 grid points, Cin=32, Cout=64,
//  K=16 neighbors, edge_in=35 (32 feat + 3 rel_pos), Cprov=96 grid channels.
#define KNN_K   16
#define CIN     32
#define COUT    64
#define CPROV   96
#define MAXM    32768
#define MAXN    8192
#define SCALE   32.0f   // RES / (aabb_max - aabb_min), uniform

#define NB      16      // bins per axis
#define NCELLS  (NB*NB*NB)
#define CSZ_SCALED 2.0f // scaled cell size = 32/16

__device__ int    g_knn[MAXM * KNN_K];
__device__ int    g_cnt[NCELLS];
__device__ int    g_start[NCELLS + 1];
__device__ int    g_cursor[NCELLS];
__device__ float4 g_pts[MAXN];        // scaled (x,y,z,|p|^2), binned order
__device__ int    g_idx[MAXN];        // original vertex index, binned order
__device__ float  g_F1[MAXN * COUT];  // feats@ew1[0:32] + eb1  (per vertex)
__device__ float4 g_aux[2 * MAXN];    // per-vertex LN stats + position:
                                      //  [2n]   = (S1, Q0, Qx, Qy)
                                      //  [2n+1] = (Qz, px, py, pz)
__device__ float  g_tab[3 * 32 * COUT]; // per-axis grid-feature @ ow1[64:160]

__device__ __forceinline__ int cell_of(float x, float y, float z) {
    int cx = min(NB - 1, max(0, (int)(x * (float)NB)));
    int cy = min(NB - 1, max(0, (int)(y * (float)NB)));
    int cz = min(NB - 1, max(0, (int)(z * (float)NB)));
    return (cx << 8) | (cy << 4) | cz;
}

// ---------------------------------------------------------------------------
// Binning: count -> scan -> scatter (scatter also re-zeroes g_cnt for the
// next graph replay; g_cnt is dead after scan reads it).
// ---------------------------------------------------------------------------
__global__ void count_kernel(const float* __restrict__ verts, int N) {
    int n = blockIdx.x * blockDim.x + threadIdx.x;
    if (n < N) {
        int c = cell_of(verts[3*n], verts[3*n+1], verts[3*n+2]);
        atomicAdd(&g_cnt[c], 1);
    }
}

__global__ __launch_bounds__(1024) void scan_kernel() {
    __shared__ int s[1024];
    int t = threadIdx.x;
    int base = t * 4;
    int c0 = g_cnt[base], c1 = g_cnt[base+1], c2 = g_cnt[base+2], c3 = g_cnt[base+3];
    int tot = c0 + c1 + c2 + c3;
    s[t] = tot;
    __syncthreads();
    for (int off = 1; off < 1024; off <<= 1) {
        int v = s[t];
        if (t >= off) v += s[t - off];
        __syncthreads();
        s[t] = v;
        __syncthreads();
    }
    int excl = s[t] - tot;
    int p0 = excl, p1 = excl + c0, p2 = p1 + c1, p3 = p2 + c2;
    g_start[base]   = p0; g_cursor[base]   = p0;
    g_start[base+1] = p1; g_cursor[base+1] = p1;
    g_start[base+2] = p2; g_cursor[base+2] = p2;
    g_start[base+3] = p3; g_cursor[base+3] = p3;
    if (t == 1023) g_start[NCELLS] = s[1023];
}

__global__ void scatter_kernel(const float* __restrict__ verts, int N) {
    int n = blockIdx.x * blockDim.x + threadIdx.x;
    if (n < NCELLS) g_cnt[n] = 0;   // reset for next replay (g_cnt dead here)
    if (n < N) {
        float x = verts[3*n], y = verts[3*n+1], z = verts[3*n+2];
        int c = cell_of(x, y, z);
        int pos = atomicAdd(&g_cursor[c], 1);
        float sx = x * SCALE, sy = y * SCALE, sz = z * SCALE;
        g_pts[pos] = make_float4(sx, sy, sz, sx*sx + sy*sy + sz*sz);
        g_idx[pos] = n;
    }
}

// ---------------------------------------------------------------------------
// Binned exact KNN, warp-coherent mapping + contiguous z-spans.
//  - g_start staged in shared (16KB) -> span bookkeeping is LDS, not L2.
//  - candidate loop software-pipelined (load i+1 while testing i).
//  - warp covers a 4x4x2 point chunk -> near-lockstep shell walks.
// ---------------------------------------------------------------------------
__global__ __launch_bounds__(256) void knn_binned_kernel(
    const float* __restrict__ gverts, int M)
{
    __shared__ int ss[NCELLS + 1];
    for (int i = threadIdx.x; i < NCELLS + 1; i += 256) ss[i] = g_start[i];
    __syncthreads();

    int b = blockIdx.x;
    int bx = b & 3, by = (b >> 2) & 3, bz = b >> 4;          // 4 x 4 x 8 blocks
    int w = threadIdx.x >> 5, l = threadIdx.x & 31;
    int ix = bx*8 + ((w & 1) << 2) + (l & 3);                // 8x8x4 per block
    int iy = by*8 + (((w >> 1) & 1) << 2) + ((l >> 2) & 3);  // warp: 4x4x2
    int iz = bz*4 + (((w >> 2) & 1) << 1) + (l >> 4);
    int m = (ix << 10) | (iy << 5) | iz;
    if (m >= M) return;

    float gx = gverts[3*m+0], gy = gverts[3*m+1], gz = gverts[3*m+2];
    float qx = gx * SCALE, qy = gy * SCALE, qz = gz * SCALE;
    float qq  = qx*qx + qy*qy + qz*qz;
    float m2x = -2.f*qx, m2y = -2.f*qy, m2z = -2.f*qz;

    int qcx = min(NB-1, max(0, (int)(gx * (float)NB)));
    int qcy = min(NB-1, max(0, (int)(gy * (float)NB)));
    int qcz = min(NB-1, max(0, (int)(gz * (float)NB)));

    float bv[KNN_K]; int bi[KNN_K];
#pragma unroll
    for (int j = 0; j < KNN_K; j++) { bv[j] = FLT_MAX; bi[j] = 0; }
    float wv = FLT_MAX; int ws = 0;

    auto process_span = [&](int cx, int cy, int zlo, int zhi) {
        int cbase = (cx << 8) | (cy << 4);
        int s = ss[cbase | zlo], e = ss[(cbase | zhi) + 1];
        if (s >= e) return;
        float4 v = g_pts[s];
        int i = s;
        for (;;) {
            int nx = i + 1;
            bool more = nx < e;
            float4 vn;
            if (more) vn = g_pts[nx];          // overlap with test below
            float d2 = fmaf(m2x, v.x, fmaf(m2y, v.y, fmaf(m2z, v.z, qq + v.w)));
            if (d2 < wv) {
                int n = g_idx[i];
#pragma unroll
                for (int j = 0; j < KNN_K; j++)
                    if (j == ws) { bv[j] = d2; bi[j] = n; }
                wv = -FLT_MAX;
#pragma unroll
                for (int j = 0; j < KNN_K; j++)
                    if (bv[j] > wv) { wv = bv[j]; ws = j; }
            }
            if (!more) break;
            v = vn; i = nx;
        }
    };

    for (int r = 0; r < NB; r++) {
        int x0 = max(qcx - r, 0), x1 = min(qcx + r, NB - 1);
        int y0 = max(qcy - r, 0), y1 = min(qcy + r, NB - 1);
        int z0 = max(qcz - r, 0), z1 = min(qcz + r, NB - 1);
        for (int cx = x0; cx <= x1; cx++) {
            bool fx = (cx == qcx - r) || (cx == qcx + r);
            for (int cy = y0; cy <= y1; cy++) {
                bool fxy = fx || (cy == qcy - r) || (cy == qcy + r);
                if (fxy) {
                    process_span(cx, cy, z0, z1);
                } else {
                    if (qcz - r >= 0)             process_span(cx, cy, qcz - r, qcz - r);
                    if (r > 0 && qcz + r <= NB-1) process_span(cx, cy, qcz + r, qcz + r);
                }
            }
        }
        float bound = CSZ_SCALED * (float)r;
        if (wv <= bound * bound) break;
    }

#pragma unroll
    for (int j = 0; j < KNN_K; j++) g_knn[m*KNN_K + j] = bi[j];
}

// ---------------------------------------------------------------------------
// Fused precompute kernel.
//  Blocks [0,1024):  F1[n] = feats[n]@ew1[0:32] + eb1 per vertex, PLUS the
//    per-vertex LN statistics:
//      S1 = sum_c F1, Q0 = sum_c F1^2, Q* = sum_c F1*ew1[32+axis],
//    and vertex position, packed in g_aux[2n], g_aux[2n+1].
//  Blocks [1024,1036): per-axis tables of gfeat@ow1[64:160] (exact separable
//    split: channel block 32a depends only on axis-a coordinate).
// ---------------------------------------------------------------------------
__global__ __launch_bounds__(256) void f1tab_kernel(
    const float* __restrict__ feats, const float* __restrict__ verts,
    const float* __restrict__ ew1,   const float* __restrict__ eb1,
    const float* __restrict__ gfeat, const float* __restrict__ ow1, int N)
{
    int w = threadIdx.x >> 5, lane = threadIdx.x & 31;
    if (blockIdx.x < 1024) {
        int n = blockIdx.x * 8 + w;
        if (n >= N) return;
        float fl = feats[n*CIN + lane];
        float2 b = ((const float2*)eb1)[lane];
        float a0 = b.x, a1 = b.y;
        const float2* w1 = (const float2*)ew1;
#pragma unroll
        for (int j = 0; j < CIN; j++) {
            float fv = __shfl_sync(0xffffffffu, fl, j);
            float2 wv = w1[j*32 + lane];
            a0 = fmaf(fv, wv.x, a0);
            a1 = fmaf(fv, wv.y, a1);
        }
        ((float2*)g_F1)[n*32 + lane] = make_float2(a0, a1);

        // LN statistics of the F1 row against rel-pos weight rows
        float2 wpx = w1[32*32 + lane];
        float2 wpy = w1[33*32 + lane];
        float2 wpz = w1[34*32 + lane];
        float s1 = a0 + a1;
        float q0 = a0*a0 + a1*a1;
        float qx = a0*wpx.x + a1*wpx.y;
        float qy = a0*wpy.x + a1*wpy.y;
        float qz = a0*wpz.x + a1*wpz.y;
#pragma unroll
        for (int o = 16; o; o >>= 1) {
            s1 += __shfl_xor_sync(0xffffffffu, s1, o);
            q0 += __shfl_xor_sync(0xffffffffu, q0, o);
            qx += __shfl_xor_sync(0xffffffffu, qx, o);
            qy += __shfl_xor_sync(0xffffffffu, qy, o);
            qz += __shfl_xor_sync(0xffffffffu, qz, o);
        }
        if (lane == 0) {
            g_aux[2*n]   = make_float4(s1, q0, qx, qy);
            g_aux[2*n+1] = make_float4(qz, verts[3*n], verts[3*n+1], verts[3*n+2]);
        }
    } else {
        int row = (blockIdx.x - 1024) * 8 + w;          // 0..95
        if (row >= 96) return;
        int a = row >> 5, i = row & 31;
        int m_sel = (a == 0) ? (i << 10) : ((a == 1) ? (i << 5) : i);
        const float* gf = gfeat + m_sel * CPROV + 32 * a;
        const float2* wo = (const float2*)(ow1 + (COUT + 32 * a) * COUT);
        float t0 = 0.f, t1 = 0.f;
#pragma unroll
        for (int j = 0; j < 32; j++) {
            float gv = gf[j];
            float2 wv = wo[j*32 + lane];
            t0 = fmaf(gv, wv.x, t0);
            t1 = fmaf(gv, wv.y, t1);
        }
        ((float2*)g_tab)[row*32 + lane] = make_float2(t0, t1);
    }
}

// ---------------------------------------------------------------------------
// Fused MLP. One warp per 4 grid points. Phase-1 LayerNorm statistics come
// from the algebraic decomposition (no warp reductions in the k-loop):
//   sum(a)  = S1 + r . SW
//   sum(a²) = Q0 + 2 r.Q + rT (sum w wT) r
// ---------------------------------------------------------------------------
__device__ __forceinline__ float gelu_fast(float x) {
    float x3 = x * x * x;
    float g = 1.5957691216057308f * fmaf(0.044715f, x3, x);   // 2*0.79788456*(...)
    float e = __expf(g);
    float t = 1.0f - __fdividef(2.0f, e + 1.0f);              // = tanh(g/2)
    return 0.5f * x * (1.0f + t);
}

#define GPW 4   // grid points per warp
#define WPB 8   // warps per block
__global__ __launch_bounds__(WPB*32) void mlp_kernel(
    const float* __restrict__ gverts, const float* __restrict__ ew1,
    const float* __restrict__ eg1,  const float* __restrict__ ebt1,
    const float* __restrict__ ew2,  const float* __restrict__ eb2,
    const float* __restrict__ ow1,  const float* __restrict__ ob1,
    const float* __restrict__ og1,  const float* __restrict__ obt1,
    const float* __restrict__ ow2,  const float* __restrict__ ob2,
    float* __restrict__ out, int M)
{
    __shared__ __align__(16) float sh_a[WPB][GPW][COUT];  // staging A
    __shared__ __align__(16) float sh_b[WPB][GPW][COUT];  // staging B

    int w = threadIdx.x >> 5, lane = threadIdx.x & 31;
    int mbase = (blockIdx.x * WPB + w) * GPW;
    if (mbase >= M) return;   // uniform per warp

    float2 wpx = ((const float2*)ew1)[32*32 + lane];
    float2 wpy = ((const float2*)ew1)[33*32 + lane];
    float2 wpz = ((const float2*)ew1)[34*32 + lane];
    float2 ge1 = ((const float2*)eg1)[lane];
    float2 bt1 = ((const float2*)ebt1)[lane];
    const float2* F1 = (const float2*)g_F1;

    // global weight moments (uniform across warp after reduction)
    float SWX = wpx.x + wpx.y, SWY = wpy.x + wpy.y, SWZ = wpz.x + wpz.y;
    float WXX = wpx.x*wpx.x + wpx.y*wpx.y;
    float WYY = wpy.x*wpy.x + wpy.y*wpy.y;
    float WZZ = wpz.x*wpz.x + wpz.y*wpz.y;
    float WXY = wpx.x*wpy.x + wpx.y*wpy.y;
    float WXZ = wpx.x*wpz.x + wpx.y*wpz.y;
    float WYZ = wpy.x*wpz.x + wpy.y*wpz.y;
#pragma unroll
    for (int o = 16; o; o >>= 1) {
        SWX += __shfl_xor_sync(0xffffffffu, SWX, o);
        SWY += __shfl_xor_sync(0xffffffffu, SWY, o);
        SWZ += __shfl_xor_sync(0xffffffffu, SWZ, o);
        WXX += __shfl_xor_sync(0xffffffffu, WXX, o);
        WYY += __shfl_xor_sync(0xffffffffu, WYY, o);
        WZZ += __shfl_xor_sync(0xffffffffu, WZZ, o);
        WXY += __shfl_xor_sync(0xffffffffu, WXY, o);
        WXZ += __shfl_xor_sync(0xffffffffu, WXZ, o);
        WYZ += __shfl_xor_sync(0xffffffffu, WYZ, o);
    }

    // ---- phase 1: per point, edge layer1 + LN + GELU + mean over K ----
#pragma unroll
    for (int p = 0; p < GPW; p++) {
        int m = mbase + p;
        float gx = gverts[3*m+0], gy = gverts[3*m+1], gz = gverts[3*m+2];
        int myn = 0;
        if (lane < KNN_K) myn = g_knn[m*KNN_K + lane];
        float gm0 = 0.f, gm1 = 0.f;
#pragma unroll
        for (int k = 0; k < KNN_K; k++) {
            int n = __shfl_sync(0xffffffffu, myn, k);
            float4 A = g_aux[2*n];        // (S1, Q0, Qx, Qy)  broadcast
            float4 B = g_aux[2*n+1];      // (Qz, px, py, pz)  broadcast
            float rx = B.y - gx, ry = B.z - gy, rz = B.w - gz;
            float s  = A.x + rx*SWX + ry*SWY + rz*SWZ;
            float s2 = A.y + 2.f*(rx*A.z + ry*A.w + rz*B.x)
                     + rx*rx*WXX + ry*ry*WYY + rz*rz*WZZ
                     + 2.f*(rx*ry*WXY + rx*rz*WXZ + ry*rz*WYZ);
            float mean = s * (1.f/COUT);
            float inv  = rsqrtf(s2 * (1.f/COUT) - mean*mean + 1e-5f);
            float2 f = F1[n*32 + lane];
            float a0 = fmaf(rx, wpx.x, fmaf(ry, wpy.x, fmaf(rz, wpz.x, f.x)));
            float a1 = fmaf(rx, wpx.y, fmaf(ry, wpy.y, fmaf(rz, wpz.y, f.y)));
            a0 = (a0 - mean) * inv * ge1.x + bt1.x;
            a1 = (a1 - mean) * inv * ge1.y + bt1.y;
            gm0 += gelu_fast(a0);
            gm1 += gelu_fast(a1);
        }
        *(float2*)&sh_a[w][p][2*lane] = make_float2(gm0 * (1.f/KNN_K), gm1 * (1.f/KNN_K));
    }
    __syncwarp();

    // ---- phase 2: edge layer 2 (hoisted past mean): 64 -> 64, x4 points ----
    {
        float2 be2 = ((const float2*)eb2)[lane];
        float a0[GPW], a1[GPW];
#pragma unroll
        for (int p = 0; p < GPW; p++) { a0[p] = be2.x; a1[p] = be2.y; }
        const float2* w2 = (const float2*)ew2;
#pragma unroll
        for (int i4 = 0; i4 < 16; i4++) {
            float2 wa = w2[(4*i4+0)*32 + lane];
            float2 wb = w2[(4*i4+1)*32 + lane];
            float2 wc = w2[(4*i4+2)*32 + lane];
            float2 wd = w2[(4*i4+3)*32 + lane];
#pragma unroll
            for (int p = 0; p < GPW; p++) {
                float4 v = ((const float4*)sh_a[w][p])[i4];
                a0[p] = fmaf(v.x, wa.x, a0[p]); a1[p] = fmaf(v.x, wa.y, a1[p]);
                a0[p] = fmaf(v.y, wb.x, a0[p]); a1[p] = fmaf(v.y, wb.y, a1[p]);
                a0[p] = fmaf(v.z, wc.x, a0[p]); a1[p] = fmaf(v.z, wc.y, a1[p]);
                a0[p] = fmaf(v.w, wd.x, a0[p]); a1[p] = fmaf(v.w, wd.y, a1[p]);
            }
        }
        __syncwarp();
#pragma unroll
        for (int p = 0; p < GPW; p++)
            *(float2*)&sh_b[w][p][2*lane] = make_float2(a0[p], a1[p]);
        __syncwarp();
    }

    // ---- phase 3: out layer 1: agg(64)@ow1[0:64] + table(ix,iy,iz), LN, GELU ----
    {
        float2 bo1 = ((const float2*)ob1)[lane];
        float c0[GPW], c1[GPW];
#pragma unroll
        for (int p = 0; p < GPW; p++) { c0[p] = bo1.x; c1[p] = bo1.y; }
        const float2* wo1 = (const float2*)ow1;
#pragma unroll
        for (int i4 = 0; i4 < 16; i4++) {
            float2 wa = wo1[(4*i4+0)*32 + lane];
            float2 wb = wo1[(4*i4+1)*32 + lane];
            float2 wc = wo1[(4*i4+2)*32 + lane];
            float2 wd = wo1[(4*i4+3)*32 + lane];
#pragma unroll
            for (int p = 0; p < GPW; p++) {
                float4 v = ((const float4*)sh_b[w][p])[i4];
                c0[p] = fmaf(v.x, wa.x, c0[p]); c1[p] = fmaf(v.x, wa.y, c1[p]);
                c0[p] = fmaf(v.y, wb.x, c0[p]); c1[p] = fmaf(v.y, wb.y, c1[p]);
                c0[p] = fmaf(v.z, wc.x, c0[p]); c1[p] = fmaf(v.z, wc.y, c1[p]);
                c0[p] = fmaf(v.w, wd.x, c0[p]); c1[p] = fmaf(v.w, wd.y, c1[p]);
            }
        }
        const float2* tab = (const float2*)g_tab;
        float2 go = ((const float2*)og1)[lane];
        float2 bo = ((const float2*)obt1)[lane];
#pragma unroll
        for (int p = 0; p < GPW; p++) {
            int m = mbase + p;
            int ix = m >> 10, iy = (m >> 5) & 31, iz = m & 31;
            float2 tx = tab[(0*32 + ix)*32 + lane];
            float2 ty = tab[(1*32 + iy)*32 + lane];
            float2 tz = tab[(2*32 + iz)*32 + lane];
            float a0 = c0[p] + tx.x + ty.x + tz.x;
            float a1 = c1[p] + tx.y + ty.y + tz.y;
            float s = a0 + a1, s2 = a0*a0 + a1*a1;
#pragma unroll
            for (int o = 16; o; o >>= 1) {
                s  += __shfl_xor_sync(0xffffffffu, s,  o);
                s2 += __shfl_xor_sync(0xffffffffu, s2, o);
            }
            float mean = s * (1.f/COUT);
            float inv  = rsqrtf(s2 * (1.f/COUT) - mean*mean + 1e-5f);
            a0 = (a0 - mean) * inv * go.x + bo.x;
            a1 = (a1 - mean) * inv * go.y + bo.y;
            *(float2*)&sh_a[w][p][2*lane] = make_float2(gelu_fast(a0), gelu_fast(a1));
        }
        __syncwarp();
    }

    // ---- phase 4: out layer 2: 64 -> 64, x4 points, store ----
    {
        float2 bo2 = ((const float2*)ob2)[lane];
        float o0[GPW], o1[GPW];
#pragma unroll
        for (int p = 0; p < GPW; p++) { o0[p] = bo2.x; o1[p] = bo2.y; }
        const float2* wo2 = (const float2*)ow2;
#pragma unroll
        for (int i4 = 0; i4 < 16; i4++) {
            float2 wa = wo2[(4*i4+0)*32 + lane];
            float2 wb = wo2[(4*i4+1)*32 + lane];
            float2 wc = wo2[(4*i4+2)*32 + lane];
            float2 wd = wo2[(4*i4+3)*32 + lane];
#pragma unroll
            for (int p = 0; p < GPW; p++) {
                float4 v = ((const float4*)sh_a[w][p])[i4];
                o0[p] = fmaf(v.x, wa.x, o0[p]); o1[p] = fmaf(v.x, wa.y, o1[p]);
                o0[p] = fmaf(v.y, wb.x, o0[p]); o1[p] = fmaf(v.y, wb.y, o1[p]);
                o0[p] = fmaf(v.z, wc.x, o0[p]); o1[p] = fmaf(v.z, wc.y, o1[p]);
                o0[p] = fmaf(v.w, wd.x, o0[p]); o1[p] = fmaf(v.w, wd.y, o1[p]);
            }
        }
#pragma unroll
        for (int p = 0; p < GPW; p++)
            ((float2*)out)[(mbase + p)*32 + lane] = make_float2(o0[p], o1[p]);
    }
}

// ---------------------------------------------------------------------------
// Launch. Input order:
//  0 vertices (1,N,3)  1 features (1,N,32)  2 grid_verts (M,3)  3 grid_feat (M,96)
//  4 ew1 (35,64) 5 eb1 6 eg1 7 ebt1 8 ew2 (64,64) 9 eb2
//  10 ow1 (160,64) 11 ob1 12 og1 13 obt1 14 ow2 (64,64) 15 ob2
// Output: (1,32,32,32,64) float32.
// ---------------------------------------------------------------------------
extern "C" void kernel_launch(void* const* d_in, const int* in_sizes, int n_in,
                              void* d_out, int out_size)
{
    const float* verts  = (const float*)d_in[0];
    const float* feats  = (const float*)d_in[1];
    const float* gverts = (const float*)d_in[2];
    const float* gfeat  = (const float*)d_in[3];
    const float* ew1  = (const float*)d_in[4];
    const float* eb1  = (const float*)d_in[5];
    const float* eg1  = (const float*)d_in[6];
    const float* ebt1 = (const float*)d_in[7];
    const float* ew2  = (const float*)d_in[8];
    const float* eb2  = (const float*)d_in[9];
    const float* ow1  = (const float*)d_in[10];
    const float* ob1  = (const float*)d_in[11];
    const float* og1  = (const float*)d_in[12];
    const float* obt1 = (const float*)d_in[13];
    const float* ow2  = (const float*)d_in[14];
    const float* ob2  = (const float*)d_in[15];

    int N = in_sizes[0] / 3;
    int M = in_sizes[2] / 3;

    count_kernel<<<(N + 255) / 256, 256>>>(verts, N);
    scan_kernel<<<1, 1024>>>();
    scatter_kernel<<<(N + 255) / 256, 256>>>(verts, N);
    knn_binned_kernel<<<128, 256>>>(gverts, M);
    f1tab_kernel<<<1036, 256>>>(feats, verts, ew1, eb1, gfeat, ow1, N);
    mlp_kernel<<<(M + WPB*GPW - 1) / (WPB*GPW), WPB * 32>>>(
        gverts, ew1,
        eg1, ebt1, ew2, eb2,
        ow1, ob1, og1, obt1, ow2, ob2,
        (float*)d_out, M);
}

// round 14
// speedup vs baseline: 3.9746x; 1.0248x over previous
#include <cuda_runtime.h>
#include <math.h>
#include <float.h>

// Problem constants (fixed by the dataset):
//  B=1, N=8192 vertices, M=32*32*32=32768 grid points, Cin=32, Cout=64,
//  K=16 neighbors, edge_in=35 (32 feat + 3 rel_pos), Cprov=96 grid channels.
#define KNN_K   16
#define CIN     32
#define COUT    64
#define CPROV   96
#define MAXM    32768
#define MAXN    8192
#define SCALE   32.0f   // RES / (aabb_max - aabb_min), uniform

#define NB      16      // bins per axis
#define NCELLS  (NB*NB*NB)

__device__ int    g_knn[MAXM * KNN_K];
__device__ int    g_cnt[NCELLS];
__device__ int    g_start[NCELLS + 1];
__device__ int    g_cursor[NCELLS];
__device__ float4 g_pts[MAXN];        // scaled (x,y,z,|p|^2), binned order
__device__ int    g_idx[MAXN];        // original vertex index, binned order
__device__ float  g_F1[MAXN * COUT];  // feats@ew1[0:32] + eb1  (per vertex)
__device__ float4 g_aux[2 * MAXN];    // per-vertex LN stats + position:
                                      //  [2n]   = (S1, Q0, Qx, Qy)
                                      //  [2n+1] = (Qz, px, py, pz)
__device__ float  g_tab[3 * 32 * COUT]; // per-axis grid-feature @ ow1[64:160]

__device__ __forceinline__ int cell_of(float x, float y, float z) {
    int cx = min(NB - 1, max(0, (int)(x * (float)NB)));
    int cy = min(NB - 1, max(0, (int)(y * (float)NB)));
    int cz = min(NB - 1, max(0, (int)(z * (float)NB)));
    return (cx << 8) | (cy << 4) | cz;
}

// ---------------------------------------------------------------------------
// Binning: count -> scan -> scatter (scatter re-zeroes g_cnt for next replay).
// ---------------------------------------------------------------------------
__global__ void count_kernel(const float* __restrict__ verts, int N) {
    int n = blockIdx.x * blockDim.x + threadIdx.x;
    if (n < N) {
        int c = cell_of(verts[3*n], verts[3*n+1], verts[3*n+2]);
        atomicAdd(&g_cnt[c], 1);
    }
}

__global__ __launch_bounds__(1024) void scan_kernel() {
    __shared__ int s[1024];
    int t = threadIdx.x;
    int base = t * 4;
    int c0 = g_cnt[base], c1 = g_cnt[base+1], c2 = g_cnt[base+2], c3 = g_cnt[base+3];
    int tot = c0 + c1 + c2 + c3;
    s[t] = tot;
    __syncthreads();
    for (int off = 1; off < 1024; off <<= 1) {
        int v = s[t];
        if (t >= off) v += s[t - off];
        __syncthreads();
        s[t] = v;
        __syncthreads();
    }
    int excl = s[t] - tot;
    int p0 = excl, p1 = excl + c0, p2 = p1 + c1, p3 = p2 + c2;
    g_start[base]   = p0; g_cursor[base]   = p0;
    g_start[base+1] = p1; g_cursor[base+1] = p1;
    g_start[base+2] = p2; g_cursor[base+2] = p2;
    g_start[base+3] = p3; g_cursor[base+3] = p3;
    if (t == 1023) g_start[NCELLS] = s[1023];
}

__global__ void scatter_kernel(const float* __restrict__ verts, int N) {
    int n = blockIdx.x * blockDim.x + threadIdx.x;
    if (n < NCELLS) g_cnt[n] = 0;   // reset for next replay (g_cnt dead here)
    if (n < N) {
        float x = verts[3*n], y = verts[3*n+1], z = verts[3*n+2];
        int c = cell_of(x, y, z);
        int pos = atomicAdd(&g_cursor[c], 1);
        float sx = x * SCALE, sy = y * SCALE, sz = z * SCALE;
        g_pts[pos] = make_float4(sx, sy, sz, sx*sx + sy*sy + sz*sz);
        g_idx[pos] = n;
    }
}

// ---------------------------------------------------------------------------
// Binned exact KNN, 4 lanes per grid point.
//  - lane&3 = candidate share (i += 4 strided -> coalesced float4 loads)
//  - per-lane DISTANCE-ONLY sorted top-16 (branch-guarded min/max insertion)
//  - shell stop: count of candidates <= (2r)^2 across the 4-lane group >= 16
//    (equivalent to 16th-smallest <= (2r)^2)
//  - bitonic merge of the 4 sorted lists -> exact threshold T = 16th smallest
//  - pass B: rescan same shells, emit indices with d2 <= T (slot via shared
//    atomic counter, capped at 16)
//  - warp covers 2x2x2 points; block covers 4x4x4 -> coherent shell walks
// ---------------------------------------------------------------------------
__global__ __launch_bounds__(256) void knn_binned_kernel(
    const float* __restrict__ gverts, int M)
{
    __shared__ int ss[NCELLS + 1];
    __shared__ int scnt[64];
    for (int i = threadIdx.x; i < NCELLS + 1; i += 256) ss[i] = g_start[i];
    if (threadIdx.x < 64) scnt[threadIdx.x] = 0;
    __syncthreads();

    int b  = blockIdx.x;                       // 512 blocks = 8x8x8
    int bx = b & 7, by = (b >> 3) & 7, bz = b >> 6;
    int w  = threadIdx.x >> 5;                 // 8 warps, each 2x2x2 points
    int lane = threadIdx.x & 31;
    int q  = lane >> 2, sub = lane & 3;        // point-in-warp, share
    int ix = bx*4 + (w & 1)*2        + (q & 1);
    int iy = by*4 + ((w >> 1) & 1)*2 + ((q >> 1) & 1);
    int iz = bz*4 + ((w >> 2) & 1)*2 + (q >> 2);
    int m  = (ix << 10) | (iy << 5) | iz;
    if (m >= M) return;
    unsigned gmask = 0xFu << (lane & 28);      // 4-lane group mask
    int pidx = threadIdx.x >> 2;               // per-block point index (0..63)

    float gx = gverts[3*m+0], gy = gverts[3*m+1], gz = gverts[3*m+2];
    float qx = gx * SCALE, qy = gy * SCALE, qz = gz * SCALE;
    float qq  = qx*qx + qy*qy + qz*qz;
    float m2x = -2.f*qx, m2y = -2.f*qy, m2z = -2.f*qz;

    int qcx = min(NB-1, max(0, (int)(gx * (float)NB)));
    int qcy = min(NB-1, max(0, (int)(gy * (float)NB)));
    int qcz = min(NB-1, max(0, (int)(gz * (float)NB)));

    float bv[KNN_K];
#pragma unroll
    for (int j = 0; j < KNN_K; j++) bv[j] = FLT_MAX;

    // enumerate the contiguous candidate spans of Chebyshev shell r
    auto shell_spans = [&](int r, auto&& fn) {
        int x0 = max(qcx - r, 0), x1 = min(qcx + r, NB - 1);
        int y0 = max(qcy - r, 0), y1 = min(qcy + r, NB - 1);
        int z0 = max(qcz - r, 0), z1 = min(qcz + r, NB - 1);
        for (int cx = x0; cx <= x1; cx++) {
            bool fx = (cx == qcx - r) || (cx == qcx + r);
            for (int cy = y0; cy <= y1; cy++) {
                bool fxy = fx || (cy == qcy - r) || (cy == qcy + r);
                int cbase = (cx << 8) | (cy << 4);
                if (fxy) {
                    fn(ss[cbase | z0], ss[(cbase | z1) + 1]);
                } else {
                    if (qcz - r >= 0) {
                        int c = cbase | (qcz - r);
                        fn(ss[c], ss[c + 1]);
                    }
                    if (r > 0 && qcz + r <= NB - 1) {
                        int c = cbase | (qcz + r);
                        fn(ss[c], ss[c + 1]);
                    }
                }
            }
        }
    };

    // ---- pass A: distances only ----
    auto scanA = [&](int s, int e) {
        for (int i = s + sub; i < e; i += 4) {
            float4 v = g_pts[i];
            float d2 = fmaf(m2x, v.x, fmaf(m2y, v.y, fmaf(m2z, v.z, qq + v.w)));
            if (d2 < bv[15]) {              // sorted insertion (asc)
                float vv = d2;
#pragma unroll
                for (int j = 0; j < KNN_K; j++) {
                    float lo = fminf(bv[j], vv);
                    vv = fmaxf(bv[j], vv);
                    bv[j] = lo;
                }
            }
        }
    };

    int rstop = NB - 1;
    for (int r = 0; r < NB; r++) {
        shell_spans(r, scanA);
        float bound2 = (float)(4 * r * r);
        int c = 0;
#pragma unroll
        for (int j = 0; j < KNN_K; j++) c += (bv[j] <= bound2) ? 1 : 0;
        c += __shfl_xor_sync(gmask, c, 1);
        c += __shfl_xor_sync(gmask, c, 2);
        if (c >= KNN_K) { rstop = r; break; }
    }

    // ---- bitonic merge of 4 sorted lists (xor 1, then xor 2) ----
#pragma unroll
    for (int stage = 1; stage <= 2; stage <<= 1) {
        float pb[KNN_K];
#pragma unroll
        for (int j = 0; j < KNN_K; j++)
            pb[j] = __shfl_xor_sync(gmask, bv[15 - j], stage);
#pragma unroll
        for (int j = 0; j < KNN_K; j++) bv[j] = fminf(bv[j], pb[j]);  // bitonic low half
#pragma unroll
        for (int s = 8; s >= 1; s >>= 1) {
#pragma unroll
            for (int j = 0; j < KNN_K; j++) {
                if ((j & s) == 0) {
                    float lo = fminf(bv[j], bv[j + s]);
                    bv[j + s] = fmaxf(bv[j], bv[j + s]);
                    bv[j] = lo;
                }
            }
        }
    }
    float T = bv[15];   // exact 16th-smallest distance (identical in all 4 lanes)

    // ---- pass B: recover identities ----
    auto scanB = [&](int s, int e) {
        for (int i = s + sub; i < e; i += 4) {
            float4 v = g_pts[i];
            float d2 = fmaf(m2x, v.x, fmaf(m2y, v.y, fmaf(m2z, v.z, qq + v.w)));
            if (d2 <= T) {
                int slot = atomicAdd(&scnt[pidx], 1);
                if (slot < KNN_K) g_knn[m*KNN_K + slot] = g_idx[i];
            }
        }
    };
    for (int r = 0; r <= rstop; r++) shell_spans(r, scanB);
}

// ---------------------------------------------------------------------------
// Fused precompute kernel.
//  Blocks [0,1024):  F1[n] = feats[n]@ew1[0:32] + eb1 per vertex, PLUS the
//    per-vertex LN statistics (S1, Q0, Qx, Qy, Qz) and position in g_aux.
//  Blocks [1024,1036): per-axis tables of gfeat@ow1[64:160] (exact separable
//    split: channel block 32a depends only on axis-a coordinate).
// ---------------------------------------------------------------------------
__global__ __launch_bounds__(256) void f1tab_kernel(
    const float* __restrict__ feats, const float* __restrict__ verts,
    const float* __restrict__ ew1,   const float* __restrict__ eb1,
    const float* __restrict__ gfeat, const float* __restrict__ ow1, int N)
{
    int w = threadIdx.x >> 5, lane = threadIdx.x & 31;
    if (blockIdx.x < 1024) {
        int n = blockIdx.x * 8 + w;
        if (n >= N) return;
        float fl = feats[n*CIN + lane];
        float2 b = ((const float2*)eb1)[lane];
        float a0 = b.x, a1 = b.y;
        const float2* w1 = (const float2*)ew1;
#pragma unroll
        for (int j = 0; j < CIN; j++) {
            float fv = __shfl_sync(0xffffffffu, fl, j);
            float2 wv = w1[j*32 + lane];
            a0 = fmaf(fv, wv.x, a0);
            a1 = fmaf(fv, wv.y, a1);
        }
        ((float2*)g_F1)[n*32 + lane] = make_float2(a0, a1);

        float2 wpx = w1[32*32 + lane];
        float2 wpy = w1[33*32 + lane];
        float2 wpz = w1[34*32 + lane];
        float s1 = a0 + a1;
        float q0 = a0*a0 + a1*a1;
        float qx = a0*wpx.x + a1*wpx.y;
        float qy = a0*wpy.x + a1*wpy.y;
        float qz = a0*wpz.x + a1*wpz.y;
#pragma unroll
        for (int o = 16; o; o >>= 1) {
            s1 += __shfl_xor_sync(0xffffffffu, s1, o);
            q0 += __shfl_xor_sync(0xffffffffu, q0, o);
            qx += __shfl_xor_sync(0xffffffffu, qx, o);
            qy += __shfl_xor_sync(0xffffffffu, qy, o);
            qz += __shfl_xor_sync(0xffffffffu, qz, o);
        }
        if (lane == 0) {
            g_aux[2*n]   = make_float4(s1, q0, qx, qy);
            g_aux[2*n+1] = make_float4(qz, verts[3*n], verts[3*n+1], verts[3*n+2]);
        }
    } else {
        int row = (blockIdx.x - 1024) * 8 + w;          // 0..95
        if (row >= 96) return;
        int a = row >> 5, i = row & 31;
        int m_sel = (a == 0) ? (i << 10) : ((a == 1) ? (i << 5) : i);
        const float* gf = gfeat + m_sel * CPROV + 32 * a;
        const float2* wo = (const float2*)(ow1 + (COUT + 32 * a) * COUT);
        float t0 = 0.f, t1 = 0.f;
#pragma unroll
        for (int j = 0; j < 32; j++) {
            float gv = gf[j];
            float2 wv = wo[j*32 + lane];
            t0 = fmaf(gv, wv.x, t0);
            t1 = fmaf(gv, wv.y, t1);
        }
        ((float2*)g_tab)[row*32 + lane] = make_float2(t0, t1);
    }
}

// ---------------------------------------------------------------------------
// Fused MLP. One warp per 4 grid points. Phase-1 LayerNorm statistics from
// the algebraic decomposition (no warp reductions in the k-loop).
// ---------------------------------------------------------------------------
__device__ __forceinline__ float gelu_fast(float x) {
    float x3 = x * x * x;
    float g = 1.5957691216057308f * fmaf(0.044715f, x3, x);   // 2*0.79788456*(...)
    float e = __expf(g);
    float t = 1.0f - __fdividef(2.0f, e + 1.0f);              // = tanh(g/2)
    return 0.5f * x * (1.0f + t);
}

#define GPW 4   // grid points per warp
#define WPB 8   // warps per block
__global__ __launch_bounds__(WPB*32) void mlp_kernel(
    const float* __restrict__ gverts, const float* __restrict__ ew1,
    const float* __restrict__ eg1,  const float* __restrict__ ebt1,
    const float* __restrict__ ew2,  const float* __restrict__ eb2,
    const float* __restrict__ ow1,  const float* __restrict__ ob1,
    const float* __restrict__ og1,  const float* __restrict__ obt1,
    const float* __restrict__ ow2,  const float* __restrict__ ob2,
    float* __restrict__ out, int M)
{
    __shared__ __align__(16) float sh_a[WPB][GPW][COUT];  // staging A
    __shared__ __align__(16) float sh_b[WPB][GPW][COUT];  // staging B

    int w = threadIdx.x >> 5, lane = threadIdx.x & 31;
    int mbase = (blockIdx.x * WPB + w) * GPW;
    if (mbase >= M) return;   // uniform per warp

    float2 wpx = ((const float2*)ew1)[32*32 + lane];
    float2 wpy = ((const float2*)ew1)[33*32 + lane];
    float2 wpz = ((const float2*)ew1)[34*32 + lane];
    float2 ge1 = ((const float2*)eg1)[lane];
    float2 bt1 = ((const float2*)ebt1)[lane];
    const float2* F1 = (const float2*)g_F1;

    // global weight moments (uniform across warp after reduction)
    float SWX = wpx.x + wpx.y, SWY = wpy.x + wpy.y, SWZ = wpz.x + wpz.y;
    float WXX = wpx.x*wpx.x + wpx.y*wpx.y;
    float WYY = wpy.x*wpy.x + wpy.y*wpy.y;
    float WZZ = wpz.x*wpz.x + wpz.y*wpz.y;
    float WXY = wpx.x*wpy.x + wpx.y*wpy.y;
    float WXZ = wpx.x*wpz.x + wpx.y*wpz.y;
    float WYZ = wpy.x*wpz.x + wpy.y*wpz.y;
#pragma unroll
    for (int o = 16; o; o >>= 1) {
        SWX += __shfl_xor_sync(0xffffffffu, SWX, o);
        SWY += __shfl_xor_sync(0xffffffffu, SWY, o);
        SWZ += __shfl_xor_sync(0xffffffffu, SWZ, o);
        WXX += __shfl_xor_sync(0xffffffffu, WXX, o);
        WYY += __shfl_xor_sync(0xffffffffu, WYY, o);
        WZZ += __shfl_xor_sync(0xffffffffu, WZZ, o);
        WXY += __shfl_xor_sync(0xffffffffu, WXY, o);
        WXZ += __shfl_xor_sync(0xffffffffu, WXZ, o);
        WYZ += __shfl_xor_sync(0xffffffffu, WYZ, o);
    }

    // ---- phase 1: per point, edge layer1 + LN + GELU + mean over K ----
#pragma unroll
    for (int p = 0; p < GPW; p++) {
        int m = mbase + p;
        float gx = gverts[3*m+0], gy = gverts[3*m+1], gz = gverts[3*m+2];
        int myn = 0;
        if (lane < KNN_K) myn = g_knn[m*KNN_K + lane];
        float gm0 = 0.f, gm1 = 0.f;
#pragma unroll
        for (int k = 0; k < KNN_K; k++) {
            int n = __shfl_sync(0xffffffffu, myn, k);
            float4 A = g_aux[2*n];        // (S1, Q0, Qx, Qy)  broadcast
            float4 B = g_aux[2*n+1];      // (Qz, px, py, pz)  broadcast
            float rx = B.y - gx, ry = B.z - gy, rz = B.w - gz;
            float s  = A.x + rx*SWX + ry*SWY + rz*SWZ;
            float s2 = A.y + 2.f*(rx*A.z + ry*A.w + rz*B.x)
                     + rx*rx*WXX + ry*ry*WYY + rz*rz*WZZ
                     + 2.f*(rx*ry*WXY + rx*rz*WXZ + ry*rz*WYZ);
            float mean = s * (1.f/COUT);
            float inv  = rsqrtf(s2 * (1.f/COUT) - mean*mean + 1e-5f);
            float2 f = F1[n*32 + lane];
            float a0 = fmaf(rx, wpx.x, fmaf(ry, wpy.x, fmaf(rz, wpz.x, f.x)));
            float a1 = fmaf(rx, wpx.y, fmaf(ry, wpy.y, fmaf(rz, wpz.y, f.y)));
            a0 = (a0 - mean) * inv * ge1.x + bt1.x;
            a1 = (a1 - mean) * inv * ge1.y + bt1.y;
            gm0 += gelu_fast(a0);
            gm1 += gelu_fast(a1);
        }
        *(float2*)&sh_a[w][p][2*lane] = make_float2(gm0 * (1.f/KNN_K), gm1 * (1.f/KNN_K));
    }
    __syncwarp();

    // ---- phase 2: edge layer 2 (hoisted past mean): 64 -> 64, x4 points ----
    {
        float2 be2 = ((const float2*)eb2)[lane];
        float a0[GPW], a1[GPW];
#pragma unroll
        for (int p = 0; p < GPW; p++) { a0[p] = be2.x; a1[p] = be2.y; }
        const float2* w2 = (const float2*)ew2;
#pragma unroll
        for (int i4 = 0; i4 < 16; i4++) {
            float2 wa = w2[(4*i4+0)*32 + lane];
            float2 wb = w2[(4*i4+1)*32 + lane];
            float2 wc = w2[(4*i4+2)*32 + lane];
            float2 wd = w2[(4*i4+3)*32 + lane];
#pragma unroll
            for (int p = 0; p < GPW; p++) {
                float4 v = ((const float4*)sh_a[w][p])[i4];
                a0[p] = fmaf(v.x, wa.x, a0[p]); a1[p] = fmaf(v.x, wa.y, a1[p]);
                a0[p] = fmaf(v.y, wb.x, a0[p]); a1[p] = fmaf(v.y, wb.y, a1[p]);
                a0[p] = fmaf(v.z, wc.x, a0[p]); a1[p] = fmaf(v.z, wc.y, a1[p]);
                a0[p] = fmaf(v.w, wd.x, a0[p]); a1[p] = fmaf(v.w, wd.y, a1[p]);
            }
        }
        __syncwarp();
#pragma unroll
        for (int p = 0; p < GPW; p++)
            *(float2*)&sh_b[w][p][2*lane] = make_float2(a0[p], a1[p]);
        __syncwarp();
    }

    // ---- phase 3: out layer 1: agg(64)@ow1[0:64] + table(ix,iy,iz), LN, GELU ----
    {
        float2 bo1 = ((const float2*)ob1)[lane];
        float c0[GPW], c1[GPW];
#pragma unroll
        for (int p = 0; p < GPW; p++) { c0[p] = bo1.x; c1[p] = bo1.y; }
        const float2* wo1 = (const float2*)ow1;
#pragma unroll
        for (int i4 = 0; i4 < 16; i4++) {
            float2 wa = wo1[(4*i4+0)*32 + lane];
            float2 wb = wo1[(4*i4+1)*32 + lane];
            float2 wc = wo1[(4*i4+2)*32 + lane];
            float2 wd = wo1[(4*i4+3)*32 + lane];
#pragma unroll
            for (int p = 0; p < GPW; p++) {
                float4 v = ((const float4*)sh_b[w][p])[i4];
                c0[p] = fmaf(v.x, wa.x, c0[p]); c1[p] = fmaf(v.x, wa.y, c1[p]);
                c0[p] = fmaf(v.y, wb.x, c0[p]); c1[p] = fmaf(v.y, wb.y, c1[p]);
                c0[p] = fmaf(v.z, wc.x, c0[p]); c1[p] = fmaf(v.z, wc.y, c1[p]);
                c0[p] = fmaf(v.w, wd.x, c0[p]); c1[p] = fmaf(v.w, wd.y, c1[p]);
            }
        }
        const float2* tab = (const float2*)g_tab;
        float2 go = ((const float2*)og1)[lane];
        float2 bo = ((const float2*)obt1)[lane];
#pragma unroll
        for (int p = 0; p < GPW; p++) {
            int m = mbase + p;
            int ix = m >> 10, iy = (m >> 5) & 31, iz = m & 31;
            float2 tx = tab[(0*32 + ix)*32 + lane];
            float2 ty = tab[(1*32 + iy)*32 + lane];
            float2 tz = tab[(2*32 + iz)*32 + lane];
            float a0 = c0[p] + tx.x + ty.x + tz.x;
            float a1 = c1[p] + tx.y + ty.y + tz.y;
            float s = a0 + a1, s2 = a0*a0 + a1*a1;
#pragma unroll
            for (int o = 16; o; o >>= 1) {
                s  += __shfl_xor_sync(0xffffffffu, s,  o);
                s2 += __shfl_xor_sync(0xffffffffu, s2, o);
            }
            float mean = s * (1.f/COUT);
            float inv  = rsqrtf(s2 * (1.f/COUT) - mean*mean + 1e-5f);
            a0 = (a0 - mean) * inv * go.x + bo.x;
            a1 = (a1 - mean) * inv * go.y + bo.y;
            *(float2*)&sh_a[w][p][2*lane] = make_float2(gelu_fast(a0), gelu_fast(a1));
        }
        __syncwarp();
    }

    // ---- phase 4: out layer 2: 64 -> 64, x4 points, store ----
    {
        float2 bo2 = ((const float2*)ob2)[lane];
        float o0[GPW], o1[GPW];
#pragma unroll
        for (int p = 0; p < GPW; p++) { o0[p] = bo2.x; o1[p] = bo2.y; }
        const float2* wo2 = (const float2*)ow2;
#pragma unroll
        for (int i4 = 0; i4 < 16; i4++) {
            float2 wa = wo2[(4*i4+0)*32 + lane];
            float2 wb = wo2[(4*i4+1)*32 + lane];
            float2 wc = wo2[(4*i4+2)*32 + lane];
            float2 wd = wo2[(4*i4+3)*32 + lane];
#pragma unroll
            for (int p = 0; p < GPW; p++) {
                float4 v = ((const float4*)sh_a[w][p])[i4];
                o0[p] = fmaf(v.x, wa.x, o0[p]); o1[p] = fmaf(v.x, wa.y, o1[p]);
                o0[p] = fmaf(v.y, wb.x, o0[p]); o1[p] = fmaf(v.y, wb.y, o1[p]);
                o0[p] = fmaf(v.z, wc.x, o0[p]); o1[p] = fmaf(v.z, wc.y, o1[p]);
                o0[p] = fmaf(v.w, wd.x, o0[p]); o1[p] = fmaf(v.w, wd.y, o1[p]);
            }
        }
#pragma unroll
        for (int p = 0; p < GPW; p++)
            ((float2*)out)[(mbase + p)*32 + lane] = make_float2(o0[p], o1[p]);
    }
}

// ---------------------------------------------------------------------------
// Launch. Input order:
//  0 vertices (1,N,3)  1 features (1,N,32)  2 grid_verts (M,3)  3 grid_feat (M,96)
//  4 ew1 (35,64) 5 eb1 6 eg1 7 ebt1 8 ew2 (64,64) 9 eb2
//  10 ow1 (160,64) 11 ob1 12 og1 13 obt1 14 ow2 (64,64) 15 ob2
// Output: (1,32,32,32,64) float32.
// ---------------------------------------------------------------------------
extern "C" void kernel_launch(void* const* d_in, const int* in_sizes, int n_in,
                              void* d_out, int out_size)
{
    const float* verts  = (const float*)d_in[0];
    const float* feats  = (const float*)d_in[1];
    const float* gverts = (const float*)d_in[2];
    const float* gfeat  = (const float*)d_in[3];
    const float* ew1  = (const float*)d_in[4];
    const float* eb1  = (const float*)d_in[5];
    const float* eg1  = (const float*)d_in[6];
    const float* ebt1 = (const float*)d_in[7];
    const float* ew2  = (const float*)d_in[8];
    const float* eb2  = (const float*)d_in[9];
    const float* ow1  = (const float*)d_in[10];
    const float* ob1  = (const float*)d_in[11];
    const float* og1  = (const float*)d_in[12];
    const float* obt1 = (const float*)d_in[13];
    const float* ow2  = (const float*)d_in[14];
    const float* ob2  = (const float*)d_in[15];

    int N = in_sizes[0] / 3;
    int M = in_sizes[2] / 3;

    count_kernel<<<(N + 255) / 256, 256>>>(verts, N);
    scan_kernel<<<1, 1024>>>();
    scatter_kernel<<<(N + 255) / 256, 256>>>(verts, N);
    knn_binned_kernel<<<512, 256>>>(gverts, M);
    f1tab_kernel<<<1036, 256>>>(feats, verts, ew1, eb1, gfeat, ow1, N);
    mlp_kernel<<<(M + WPB*GPW - 1) / (WPB*GPW), WPB * 32>>>(
        gverts, ew1,
        eg1, ebt1, ew2, eb2,
        ow1, ob1, og1, obt1, ow2, ob2,
        (float*)d_out, M);
}